// round 6
// baseline (speedup 1.0000x reference)
#include <cuda_runtime.h>

#define H     256
#define SEQL  10
#define BQ    2048
#define NTOT  327680
#define NSEG  (BQ * SEQL)  // 20480
#define NENT  20000

// ---------------- scratch (no cudaMalloc allowed) ----------------
__device__ float g_EW1[NENT * H];      // ent_embeds @ W1   (20.5 MB)
__device__ float g_A[BQ * H];          // s@W2 + r@W3 + b   (2 MB)
__device__ float g_scores[NTOT];       // spill store for huge segments (rare)
__device__ int   g_starts[NSEG + 1];   // segment start offsets

// Packed fp32x2 FMA (Blackwell): two fp32 FMAs per instruction.
__device__ __forceinline__ float2 ffma2(float2 a, float2 b, float2 c) {
    float2 d;
    asm("fma.rn.f32x2 %0, %1, %2, %3;"
        : "=l"(reinterpret_cast<unsigned long long&>(d))
        : "l"(reinterpret_cast<const unsigned long long&>(a)),
          "l"(reinterpret_cast<const unsigned long long&>(b)),
          "l"(reinterpret_cast<const unsigned long long&>(c)));
    return d;
}

__device__ __forceinline__ float tanh_fast(float x) {
    float y;
    asm("tanh.approx.f32 %0, %1;" : "=f"(y) : "f"(x));
    return y;
}

__device__ __forceinline__ float2 f2lo(float4 v) { return make_float2(v.x, v.y); }
__device__ __forceinline__ float2 f2hi(float4 v) { return make_float2(v.z, v.w); }

// ===========================================================================
// Kernel 1: EW1 = ent_embeds @ W1 (rows 0..255 of W).
// BM=64 x BN=128 x BK=16, 256 threads, grid (313, 2) = 626 blocks.
// Register-prefetch double buffering: next chunk's LDGs are issued before
// computing the current chunk; STS happens after the barrier.
// sA rows = dup-pair float4 {ak,ak,ak+1,ak+1}, row stride 9 (pad) -> no
// bank conflicts on staging or compute.
// ===========================================================================
#define BM 64
#define BN 128
#define BK 16
#define SAW (BK / 2 + 1)   // 9 float4 per sA row

__global__ void __launch_bounds__(256, 3)
ew1_kernel(const float* __restrict__ ent, const float* __restrict__ W) {
    __shared__ float4 sA[BM * SAW];       // 9 KB
    __shared__ float4 sW[BK * (BN / 4)];  // 8 KB
    const int tid   = threadIdx.x;
    const int tm    = tid >> 4;            // 0..15 (4 rows each)
    const int tn    = tid & 15;            // 0..15 (8 cols each, split)
    const int eBase = blockIdx.x * BM;
    const int nBase = blockIdx.y * BN;

    // staging indices
    const int se  = tid >> 2;              // 0..63   (A row)
    const int sk4 = tid & 3;               // 0..3    (A k-quad)
    const int swk = tid >> 4;              // 0..15   (W k-row)
    const int swc = tid & 15;              // W col quad base (2 per thread)

    const int aRow = min(eBase + se, NENT - 1);   // clamp: garbage rows unused

    float2 acc[4][4];
#pragma unroll
    for (int e = 0; e < 4; e++)
#pragma unroll
        for (int j = 0; j < 4; j++) acc[e][j] = make_float2(0.f, 0.f);

    // prefetch chunk 0
    float4 pa = *reinterpret_cast<const float4*>(ent + (size_t)aRow * H + sk4 * 4);
    float4 pw0 = *(reinterpret_cast<const float4*>(W + (size_t)swk * H + nBase) + swc);
    float4 pw1 = *(reinterpret_cast<const float4*>(W + (size_t)swk * H + nBase) + 16 + swc);

#pragma unroll 1
    for (int kc = 0; kc < H; kc += BK) {
        if (kc) __syncthreads();           // previous compute done, buffers free
        sA[se * SAW + sk4 * 2 + 0] = make_float4(pa.x, pa.x, pa.y, pa.y);
        sA[se * SAW + sk4 * 2 + 1] = make_float4(pa.z, pa.z, pa.w, pa.w);
        sW[swk * (BN / 4) + swc]      = pw0;
        sW[swk * (BN / 4) + 16 + swc] = pw1;
        __syncthreads();

        if (kc + BK < H) {                 // prefetch next chunk (hidden by compute)
            pa  = *reinterpret_cast<const float4*>(
                      ent + (size_t)aRow * H + (kc + BK) + sk4 * 4);
            pw0 = *(reinterpret_cast<const float4*>(
                      W + (size_t)(kc + BK + swk) * H + nBase) + swc);
            pw1 = *(reinterpret_cast<const float4*>(
                      W + (size_t)(kc + BK + swk) * H + nBase) + 16 + swc);
        }

#pragma unroll
        for (int k2 = 0; k2 < BK / 2; k2++) {
            const float4 wA0 = sW[(2 * k2) * (BN / 4) + tn];
            const float4 wB0 = sW[(2 * k2) * (BN / 4) + 16 + tn];
            const float4 wA1 = sW[(2 * k2 + 1) * (BN / 4) + tn];
            const float4 wB1 = sW[(2 * k2 + 1) * (BN / 4) + 16 + tn];
#pragma unroll
            for (int e = 0; e < 4; e++) {
                const float4 a = sA[(tm * 4 + e) * SAW + k2];   // {ak,ak,ak1,ak1}
                const float2 a0 = f2lo(a), a1 = f2hi(a);
                acc[e][0] = ffma2(a0, f2lo(wA0), acc[e][0]);
                acc[e][1] = ffma2(a0, f2hi(wA0), acc[e][1]);
                acc[e][2] = ffma2(a0, f2lo(wB0), acc[e][2]);
                acc[e][3] = ffma2(a0, f2hi(wB0), acc[e][3]);
                acc[e][0] = ffma2(a1, f2lo(wA1), acc[e][0]);
                acc[e][1] = ffma2(a1, f2hi(wA1), acc[e][1]);
                acc[e][2] = ffma2(a1, f2lo(wB1), acc[e][2]);
                acc[e][3] = ffma2(a1, f2hi(wB1), acc[e][3]);
            }
        }
    }

#pragma unroll
    for (int e = 0; e < 4; e++) {
        const int ei = eBase + tm * 4 + e;
        if (ei < NENT) {
            float* row = g_EW1 + (size_t)ei * H + nBase;
            *reinterpret_cast<float4*>(row + tn * 4) =
                make_float4(acc[e][0].x, acc[e][0].y, acc[e][1].x, acc[e][1].y);
            *reinterpret_cast<float4*>(row + 64 + tn * 4) =
                make_float4(acc[e][2].x, acc[e][2].y, acc[e][3].x, acc[e][3].y);
        }
    }
}

// ===========================================================================
// Kernel 2: A = [s_emb | r_emb] @ W[256:768] + b.  64x64 tiles -> 128 blocks.
// ===========================================================================
#define QBM 64
#define QBN 64
__global__ void __launch_bounds__(256)
aq_kernel(const int* __restrict__ s, const int* __restrict__ r,
          const float* __restrict__ ent, const float* __restrict__ rel,
          const float* __restrict__ W, const float* __restrict__ b) {
    __shared__ float4 sA[QBM * SAW];       // 9 KB
    __shared__ float4 sW[BK * (QBN / 4)];  // 4 KB
    __shared__ int sidx[QBM], ridx[QBM];
    const int tid   = threadIdx.x;
    const int tm    = tid >> 4;
    const int tn    = tid & 15;
    const int qBase = blockIdx.x * QBM;
    const int nBase = blockIdx.y * QBN;

    if (tid < QBM) { sidx[tid] = s[qBase + tid]; ridx[tid] = r[qBase + tid]; }
    __syncthreads();

    float2 acc[4][2];
#pragma unroll
    for (int e = 0; e < 4; e++) {
        acc[e][0] = make_float2(0.f, 0.f);
        acc[e][1] = make_float2(0.f, 0.f);
    }

#pragma unroll 1
    for (int kc = 0; kc < 2 * H; kc += BK) {
        __syncthreads();
        {   // stage A: 64 rows x 16 k = 256 float4 -> 1 per thread
            const int e  = tid >> 2;
            const int k4 = tid & 3;
            const float* src = (kc < H)
                ? ent + (size_t)sidx[e] * H + kc
                : rel + (size_t)ridx[e] * H + (kc - H);
            const float4 v = *reinterpret_cast<const float4*>(src + k4 * 4);
            sA[e * SAW + k4 * 2 + 0] = make_float4(v.x, v.x, v.y, v.y);
            sA[e * SAW + k4 * 2 + 1] = make_float4(v.z, v.z, v.w, v.w);
        }
        {   // stage W: 16 k-rows x 64 cols = 256 float4 -> 1 per thread
            const int kk = tid >> 4;
            const int c4 = tid & 15;
            sW[kk * (QBN / 4) + c4] = *(reinterpret_cast<const float4*>(
                W + (size_t)(H + kc + kk) * H + nBase) + c4);
        }
        __syncthreads();

#pragma unroll
        for (int k2 = 0; k2 < BK / 2; k2++) {
            const float4 w0 = sW[(2 * k2) * (QBN / 4) + tn];
            const float4 w1 = sW[(2 * k2 + 1) * (QBN / 4) + tn];
#pragma unroll
            for (int e = 0; e < 4; e++) {
                const float4 a = sA[(tm * 4 + e) * SAW + k2];
                acc[e][0] = ffma2(f2lo(a), f2lo(w0), acc[e][0]);
                acc[e][1] = ffma2(f2lo(a), f2hi(w0), acc[e][1]);
                acc[e][0] = ffma2(f2hi(a), f2lo(w1), acc[e][0]);
                acc[e][1] = ffma2(f2hi(a), f2hi(w1), acc[e][1]);
            }
        }
    }

    const float4 b4 = *reinterpret_cast<const float4*>(b + nBase + tn * 4);
#pragma unroll
    for (int e = 0; e < 4; e++) {
        float* row = g_A + (size_t)(qBase + tm * 4 + e) * H + nBase;
        *reinterpret_cast<float4*>(row + tn * 4) =
            make_float4(acc[e][0].x + b4.x, acc[e][0].y + b4.y,
                        acc[e][1].x + b4.z, acc[e][1].y + b4.w);
    }
}

// ---------------------------------------------------------------------------
// Kernel 3: segment start offsets from sorted seg_ids.
// ---------------------------------------------------------------------------
__global__ void starts_kernel(const int* __restrict__ seg_ids) {
    const int i = blockIdx.x * blockDim.x + threadIdx.x;
    if (i >= NTOT) return;
    const int cur  = seg_ids[i];
    const int prev = (i == 0) ? -1 : seg_ids[i - 1];
    for (int sg = prev + 1; sg <= cur; sg++) g_starts[sg] = i;
    if (i == NTOT - 1)
        for (int sg = cur + 1; sg <= NSEG; sg++) g_starts[sg] = NTOT;
}

// ---------------------------------------------------------------------------
// Kernel 4 (FUSED score + softmax + aggregate + assemble): block per segment.
// Pass 1: warps score neighbors (EW1 gather + MUFU.TANH), exp -> smem cache,
//         per-warp partial dsum. (No max pass: |score| <= sum|v| ~ 10.)
// Pass 2: thread-per-h weighted gather of ent rows + output assembly.
// Segments > SCAP spill exp-scores through g_scores (correct, ~never taken).
// ---------------------------------------------------------------------------
#define SCAP 512
__global__ void scoreagg_kernel(const int* __restrict__ s, const int* __restrict__ r,
                                const int* __restrict__ nbr_ids,
                                const float* __restrict__ ent,
                                const float* __restrict__ rel,
                                const float* __restrict__ v,
                                float* __restrict__ out) {
    const int seg  = blockIdx.x;
    const int tid  = threadIdx.x;          // 256
    const int w    = tid >> 5;
    const int lane = tid & 31;
    const int lo   = g_starts[seg];
    const int hi   = g_starts[seg + 1];
    const int cnt  = hi - lo;

    float* row = out + (size_t)seg * (3 * H);
    if (cnt <= 0) {
        row[tid] = 0.0f; row[H + tid] = 0.0f; row[2 * H + tid] = 0.0f;
        return;
    }
    const int q = seg / SEQL;

    __shared__ float wsm[SCAP];
    __shared__ int   nsm[SCAP];
    __shared__ float red[8];

    // ---- pass 1: scores ----
    {
        const float4* aq = reinterpret_cast<const float4*>(g_A + (size_t)q * H);
        const float4* vv = reinterpret_cast<const float4*>(v);
        const float4 a0 = aq[lane], a1 = aq[lane + 32];
        const float4 v0 = vv[lane], v1 = vv[lane + 32];

        float dsum_w = 0.0f;
        for (int j = lo + w; j < hi; j += 8) {
            const int nbr = nbr_ids[j];
            const float4* ew = reinterpret_cast<const float4*>(
                                   g_EW1 + (size_t)nbr * H);
            const float4 e0 = ew[lane], e1 = ew[lane + 32];
            float sc;
            sc = tanh_fast(e0.x + a0.x) * v0.x;
            sc = fmaf(tanh_fast(e0.y + a0.y), v0.y, sc);
            sc = fmaf(tanh_fast(e0.z + a0.z), v0.z, sc);
            sc = fmaf(tanh_fast(e0.w + a0.w), v0.w, sc);
            sc = fmaf(tanh_fast(e1.x + a1.x), v1.x, sc);
            sc = fmaf(tanh_fast(e1.y + a1.y), v1.y, sc);
            sc = fmaf(tanh_fast(e1.z + a1.z), v1.z, sc);
            sc = fmaf(tanh_fast(e1.w + a1.w), v1.w, sc);
#pragma unroll
            for (int o = 16; o; o >>= 1) sc += __shfl_xor_sync(0xffffffffu, sc, o);
            const float e = __expf(sc);
            dsum_w += e;
            if (lane == 0) {
                const int k = j - lo;
                if (k < SCAP) { wsm[k] = e; nsm[k] = nbr; }
                else          g_scores[j] = e;            // spill (rare)
            }
        }
        if (lane == 0) red[w] = dsum_w;
    }
    __syncthreads();

    float dsum = red[0];
#pragma unroll
    for (int i = 1; i < 8; i++) dsum += red[i];
    const float inv = 1.0f / dsum;

    // ---- pass 2: weighted gather, thread owns h = tid ----
    float a0 = 0.f, a1 = 0.f, a2 = 0.f, a3 = 0.f;
    const int c = min(cnt, SCAP);
    int jj = 0;
    for (; jj + 4 <= c; jj += 4) {
        a0 = fmaf(wsm[jj + 0], ent[(size_t)nsm[jj + 0] * H + tid], a0);
        a1 = fmaf(wsm[jj + 1], ent[(size_t)nsm[jj + 1] * H + tid], a1);
        a2 = fmaf(wsm[jj + 2], ent[(size_t)nsm[jj + 2] * H + tid], a2);
        a3 = fmaf(wsm[jj + 3], ent[(size_t)nsm[jj + 3] * H + tid], a3);
    }
    for (; jj < c; jj++)
        a0 = fmaf(wsm[jj], ent[(size_t)nsm[jj] * H + tid], a0);
    for (; jj < cnt; jj++)                               // spill path (rare)
        a0 = fmaf(g_scores[lo + jj], ent[(size_t)nbr_ids[lo + jj] * H + tid], a0);

    row[tid]         = ((a0 + a1) + (a2 + a3)) * inv;
    row[H + tid]     = ent[(size_t)s[q] * H + tid];
    row[2 * H + tid] = rel[(size_t)r[q] * H + tid];
}

// ---------------------------------------------------------------------------
extern "C" void kernel_launch(void* const* d_in, const int* in_sizes, int n_in,
                              void* d_out, int out_size) {
    const int*   s    = (const int*)d_in[0];
    const int*   r    = (const int*)d_in[1];
    const int*   nbr  = (const int*)d_in[2];
    const int*   segi = (const int*)d_in[3];
    const float* ent  = (const float*)d_in[4];
    const float* rel  = (const float*)d_in[5];
    const float* W    = (const float*)d_in[6];
    const float* b    = (const float*)d_in[7];
    const float* v    = (const float*)d_in[8];
    float* out = (float*)d_out;

    starts_kernel<<<(NTOT + 255) / 256, 256>>>(segi);
    ew1_kernel<<<dim3((NENT + BM - 1) / BM, H / BN), 256>>>(ent, W);
    aq_kernel<<<dim3(BQ / QBM, H / QBN), 256>>>(s, r, ent, rel, W, b);
    scoreagg_kernel<<<NSEG, 256>>>(s, r, nbr, ent, rel, v, out);
}

// round 7
// speedup vs baseline: 1.1542x; 1.1542x over previous
#include <cuda_runtime.h>

#define H     256
#define SEQL  10
#define BQ    2048
#define NTOT  327680
#define NSEG  (BQ * SEQL)  // 20480
#define NENT  20000

// ---------------- scratch (no cudaMalloc allowed) ----------------
__device__ float g_EW1[NENT * H];      // ent_embeds @ W1   (20.5 MB)
__device__ float g_A[BQ * H];          // s@W2 + r@W3 + b   (2 MB)
__device__ float g_scores[NTOT];       // spill store for huge queries (rare)
__device__ int   g_starts[NSEG + 1];   // segment start offsets

// Packed fp32x2 FMA (Blackwell): two fp32 FMAs per instruction.
__device__ __forceinline__ float2 ffma2(float2 a, float2 b, float2 c) {
    float2 d;
    asm("fma.rn.f32x2 %0, %1, %2, %3;"
        : "=l"(reinterpret_cast<unsigned long long&>(d))
        : "l"(reinterpret_cast<const unsigned long long&>(a)),
          "l"(reinterpret_cast<const unsigned long long&>(b)),
          "l"(reinterpret_cast<const unsigned long long&>(c)));
    return d;
}

__device__ __forceinline__ float tanh_fast(float x) {
    float y;
    asm("tanh.approx.f32 %0, %1;" : "=f"(y) : "f"(x));
    return y;
}

__device__ __forceinline__ float2 f2lo(float4 v) { return make_float2(v.x, v.y); }
__device__ __forceinline__ float2 f2hi(float4 v) { return make_float2(v.z, v.w); }

// ===========================================================================
// Kernel 1: EW1 = ent_embeds @ W1 (rows 0..255 of W).
// BM=64 x BN=128 x BK=16, 256 threads, register-prefetch double buffering.
// ===========================================================================
#define BM 64
#define BN 128
#define BK 16
#define SAW (BK / 2 + 1)   // 9 float4 per sA row

__global__ void __launch_bounds__(256, 3)
ew1_kernel(const float* __restrict__ ent, const float* __restrict__ W) {
    __shared__ float4 sA[BM * SAW];       // 9 KB
    __shared__ float4 sW[BK * (BN / 4)];  // 8 KB
    const int tid   = threadIdx.x;
    const int tm    = tid >> 4;
    const int tn    = tid & 15;
    const int eBase = blockIdx.x * BM;
    const int nBase = blockIdx.y * BN;

    const int se  = tid >> 2;
    const int sk4 = tid & 3;
    const int swk = tid >> 4;
    const int swc = tid & 15;
    const int aRow = min(eBase + se, NENT - 1);

    float2 acc[4][4];
#pragma unroll
    for (int e = 0; e < 4; e++)
#pragma unroll
        for (int j = 0; j < 4; j++) acc[e][j] = make_float2(0.f, 0.f);

    float4 pa  = *reinterpret_cast<const float4*>(ent + (size_t)aRow * H + sk4 * 4);
    float4 pw0 = *(reinterpret_cast<const float4*>(W + (size_t)swk * H + nBase) + swc);
    float4 pw1 = *(reinterpret_cast<const float4*>(W + (size_t)swk * H + nBase) + 16 + swc);

#pragma unroll 1
    for (int kc = 0; kc < H; kc += BK) {
        if (kc) __syncthreads();
        sA[se * SAW + sk4 * 2 + 0] = make_float4(pa.x, pa.x, pa.y, pa.y);
        sA[se * SAW + sk4 * 2 + 1] = make_float4(pa.z, pa.z, pa.w, pa.w);
        sW[swk * (BN / 4) + swc]      = pw0;
        sW[swk * (BN / 4) + 16 + swc] = pw1;
        __syncthreads();

        if (kc + BK < H) {
            pa  = *reinterpret_cast<const float4*>(
                      ent + (size_t)aRow * H + (kc + BK) + sk4 * 4);
            pw0 = *(reinterpret_cast<const float4*>(
                      W + (size_t)(kc + BK + swk) * H + nBase) + swc);
            pw1 = *(reinterpret_cast<const float4*>(
                      W + (size_t)(kc + BK + swk) * H + nBase) + 16 + swc);
        }

#pragma unroll
        for (int k2 = 0; k2 < BK / 2; k2++) {
            const float4 wA0 = sW[(2 * k2) * (BN / 4) + tn];
            const float4 wB0 = sW[(2 * k2) * (BN / 4) + 16 + tn];
            const float4 wA1 = sW[(2 * k2 + 1) * (BN / 4) + tn];
            const float4 wB1 = sW[(2 * k2 + 1) * (BN / 4) + 16 + tn];
#pragma unroll
            for (int e = 0; e < 4; e++) {
                const float4 a = sA[(tm * 4 + e) * SAW + k2];
                const float2 a0 = f2lo(a), a1 = f2hi(a);
                acc[e][0] = ffma2(a0, f2lo(wA0), acc[e][0]);
                acc[e][1] = ffma2(a0, f2hi(wA0), acc[e][1]);
                acc[e][2] = ffma2(a0, f2lo(wB0), acc[e][2]);
                acc[e][3] = ffma2(a0, f2hi(wB0), acc[e][3]);
                acc[e][0] = ffma2(a1, f2lo(wA1), acc[e][0]);
                acc[e][1] = ffma2(a1, f2hi(wA1), acc[e][1]);
                acc[e][2] = ffma2(a1, f2lo(wB1), acc[e][2]);
                acc[e][3] = ffma2(a1, f2hi(wB1), acc[e][3]);
            }
        }
    }

#pragma unroll
    for (int e = 0; e < 4; e++) {
        const int ei = eBase + tm * 4 + e;
        if (ei < NENT) {
            float* row = g_EW1 + (size_t)ei * H + nBase;
            *reinterpret_cast<float4*>(row + tn * 4) =
                make_float4(acc[e][0].x, acc[e][0].y, acc[e][1].x, acc[e][1].y);
            *reinterpret_cast<float4*>(row + 64 + tn * 4) =
                make_float4(acc[e][2].x, acc[e][2].y, acc[e][3].x, acc[e][3].y);
        }
    }
}

// ===========================================================================
// Kernel 2: A = [s_emb | r_emb] @ W[256:768] + b.  64x64 tiles -> 128 blocks.
// ===========================================================================
#define QBM 64
#define QBN 64
__global__ void __launch_bounds__(256)
aq_kernel(const int* __restrict__ s, const int* __restrict__ r,
          const float* __restrict__ ent, const float* __restrict__ rel,
          const float* __restrict__ W, const float* __restrict__ b) {
    __shared__ float4 sA[QBM * SAW];
    __shared__ float4 sW[BK * (QBN / 4)];
    __shared__ int sidx[QBM], ridx[QBM];
    const int tid   = threadIdx.x;
    const int tm    = tid >> 4;
    const int tn    = tid & 15;
    const int qBase = blockIdx.x * QBM;
    const int nBase = blockIdx.y * QBN;

    if (tid < QBM) { sidx[tid] = s[qBase + tid]; ridx[tid] = r[qBase + tid]; }
    __syncthreads();

    float2 acc[4][2];
#pragma unroll
    for (int e = 0; e < 4; e++) {
        acc[e][0] = make_float2(0.f, 0.f);
        acc[e][1] = make_float2(0.f, 0.f);
    }

#pragma unroll 1
    for (int kc = 0; kc < 2 * H; kc += BK) {
        __syncthreads();
        {
            const int e  = tid >> 2;
            const int k4 = tid & 3;
            const float* src = (kc < H)
                ? ent + (size_t)sidx[e] * H + kc
                : rel + (size_t)ridx[e] * H + (kc - H);
            const float4 v = *reinterpret_cast<const float4*>(src + k4 * 4);
            sA[e * SAW + k4 * 2 + 0] = make_float4(v.x, v.x, v.y, v.y);
            sA[e * SAW + k4 * 2 + 1] = make_float4(v.z, v.z, v.w, v.w);
        }
        {
            const int kk = tid >> 4;
            const int c4 = tid & 15;
            sW[kk * (QBN / 4) + c4] = *(reinterpret_cast<const float4*>(
                W + (size_t)(H + kc + kk) * H + nBase) + c4);
        }
        __syncthreads();

#pragma unroll
        for (int k2 = 0; k2 < BK / 2; k2++) {
            const float4 w0 = sW[(2 * k2) * (QBN / 4) + tn];
            const float4 w1 = sW[(2 * k2 + 1) * (QBN / 4) + tn];
#pragma unroll
            for (int e = 0; e < 4; e++) {
                const float4 a = sA[(tm * 4 + e) * SAW + k2];
                acc[e][0] = ffma2(f2lo(a), f2lo(w0), acc[e][0]);
                acc[e][1] = ffma2(f2lo(a), f2hi(w0), acc[e][1]);
                acc[e][0] = ffma2(f2hi(a), f2lo(w1), acc[e][0]);
                acc[e][1] = ffma2(f2hi(a), f2hi(w1), acc[e][1]);
            }
        }
    }

    const float4 b4 = *reinterpret_cast<const float4*>(b + nBase + tn * 4);
#pragma unroll
    for (int e = 0; e < 4; e++) {
        float* row = g_A + (size_t)(qBase + tm * 4 + e) * H + nBase;
        *reinterpret_cast<float4*>(row + tn * 4) =
            make_float4(acc[e][0].x + b4.x, acc[e][0].y + b4.y,
                        acc[e][1].x + b4.z, acc[e][1].y + b4.w);
    }
}

// ---------------------------------------------------------------------------
// Kernel 3: segment start offsets from sorted seg_ids.
// ---------------------------------------------------------------------------
__global__ void starts_kernel(const int* __restrict__ seg_ids) {
    const int i = blockIdx.x * blockDim.x + threadIdx.x;
    if (i >= NTOT) return;
    const int cur  = seg_ids[i];
    const int prev = (i == 0) ? -1 : seg_ids[i - 1];
    for (int sg = prev + 1; sg <= cur; sg++) g_starts[sg] = i;
    if (i == NTOT - 1)
        for (int sg = cur + 1; sg <= NSEG; sg++) g_starts[sg] = NTOT;
}

// ---------------------------------------------------------------------------
// Kernel 4 (FUSED, QUERY-PER-BLOCK): block = one query (10 segments,
// ~160 neighbors). 256 threads.
//  Pass 1: 8 warps stride the query's neighbors: score = v.tanh(EW1[n]+A[q]),
//          exp -> smem (A[q], v in registers; no max pass, |score|<~10).
//  Mid:    10 per-segment exp-sums via tiny warp reductions.
//  Pass 2: thread-per-h: for each segment, weighted gather of ent rows,
//          emit [agg | s_emb | r_emb] (zeros for empty segments).
// Queries with > QCAP neighbors spill exp-scores via g_scores (correct, rare).
// ---------------------------------------------------------------------------
#define QCAP 512
__global__ void __launch_bounds__(256)
scoreagg_kernel(const int* __restrict__ s, const int* __restrict__ r,
                const int* __restrict__ nbr_ids,
                const float* __restrict__ ent,
                const float* __restrict__ rel,
                const float* __restrict__ v,
                float* __restrict__ out) {
    const int q    = blockIdx.x;
    const int tid  = threadIdx.x;
    const int w    = tid >> 5;
    const int lane = tid & 31;

    __shared__ int   sbnd[SEQL + 1];
    __shared__ float wsm[QCAP];
    __shared__ int   nsm[QCAP];
    __shared__ float sdsum[SEQL];

    if (tid <= SEQL) sbnd[tid] = g_starts[q * SEQL + tid];
    __syncthreads();
    const int qlo  = sbnd[0];
    const int qhi  = sbnd[SEQL];
    const int qcnt = qhi - qlo;

    // ---- pass 1: scores for all neighbors of this query ----
    if (qcnt > 0) {
        const float4* aq = reinterpret_cast<const float4*>(g_A + (size_t)q * H);
        const float4* vv = reinterpret_cast<const float4*>(v);
        const float4 a0 = aq[lane], a1 = aq[lane + 32];
        const float4 v0 = vv[lane], v1 = vv[lane + 32];

        for (int j = qlo + w; j < qhi; j += 8) {
            const int nbr = nbr_ids[j];
            const float4* ew = reinterpret_cast<const float4*>(
                                   g_EW1 + (size_t)nbr * H);
            const float4 e0 = ew[lane], e1 = ew[lane + 32];
            float sc;
            sc = tanh_fast(e0.x + a0.x) * v0.x;
            sc = fmaf(tanh_fast(e0.y + a0.y), v0.y, sc);
            sc = fmaf(tanh_fast(e0.z + a0.z), v0.z, sc);
            sc = fmaf(tanh_fast(e0.w + a0.w), v0.w, sc);
            sc = fmaf(tanh_fast(e1.x + a1.x), v1.x, sc);
            sc = fmaf(tanh_fast(e1.y + a1.y), v1.y, sc);
            sc = fmaf(tanh_fast(e1.z + a1.z), v1.z, sc);
            sc = fmaf(tanh_fast(e1.w + a1.w), v1.w, sc);
#pragma unroll
            for (int o = 16; o; o >>= 1) sc += __shfl_xor_sync(0xffffffffu, sc, o);
            if (lane == 0) {
                const float e = __expf(sc);
                const int k = j - qlo;
                if (k < QCAP) { wsm[k] = e; nsm[k] = nbr; }
                else          g_scores[j] = e;            // spill (rare)
            }
        }
    }
    __syncthreads();

    // ---- per-segment exp sums (segment sizes ~16) ----
    for (int t = w; t < SEQL; t += 8) {
        const int slo = sbnd[t]     - qlo;
        const int shi = sbnd[t + 1] - qlo;
        float d = 0.0f;
        for (int k = slo + lane; k < shi; k += 32)
            d += (k < QCAP) ? wsm[k] : g_scores[qlo + k];
#pragma unroll
        for (int o = 16; o; o >>= 1) d += __shfl_xor_sync(0xffffffffu, d, o);
        if (lane == 0) sdsum[t] = d;
    }

    // s_emb / r_emb for this query (read once, reused for all 10 rows)
    const float se = ent[(size_t)s[q] * H + tid];
    const float re = rel[(size_t)r[q] * H + tid];
    __syncthreads();

    // ---- pass 2: thread-per-h weighted gather, all segments ----
    float* qout = out + (size_t)q * SEQL * (3 * H);
#pragma unroll 1
    for (int t = 0; t < SEQL; t++) {
        float* row = qout + (size_t)t * (3 * H);
        const int slo = sbnd[t]     - qlo;
        const int shi = sbnd[t + 1] - qlo;
        if (slo >= shi) {
            row[tid] = 0.0f; row[H + tid] = 0.0f; row[2 * H + tid] = 0.0f;
            continue;
        }
        const float inv = 1.0f / sdsum[t];
        const int c = min(shi, QCAP);

        float a0 = 0.f, a1 = 0.f, a2 = 0.f, a3 = 0.f;
        int k = slo;
        for (; k + 4 <= c; k += 4) {
            a0 = fmaf(wsm[k + 0], ent[(size_t)nsm[k + 0] * H + tid], a0);
            a1 = fmaf(wsm[k + 1], ent[(size_t)nsm[k + 1] * H + tid], a1);
            a2 = fmaf(wsm[k + 2], ent[(size_t)nsm[k + 2] * H + tid], a2);
            a3 = fmaf(wsm[k + 3], ent[(size_t)nsm[k + 3] * H + tid], a3);
        }
        for (; k < c; k++)
            a0 = fmaf(wsm[k], ent[(size_t)nsm[k] * H + tid], a0);
        for (; k < shi; k++)                               // spill path (rare)
            a0 = fmaf(g_scores[qlo + k],
                      ent[(size_t)nbr_ids[qlo + k] * H + tid], a0);

        row[tid]         = ((a0 + a1) + (a2 + a3)) * inv;
        row[H + tid]     = se;
        row[2 * H + tid] = re;
    }
}

// ---------------------------------------------------------------------------
extern "C" void kernel_launch(void* const* d_in, const int* in_sizes, int n_in,
                              void* d_out, int out_size) {
    const int*   s    = (const int*)d_in[0];
    const int*   r    = (const int*)d_in[1];
    const int*   nbr  = (const int*)d_in[2];
    const int*   segi = (const int*)d_in[3];
    const float* ent  = (const float*)d_in[4];
    const float* rel  = (const float*)d_in[5];
    const float* W    = (const float*)d_in[6];
    const float* b    = (const float*)d_in[7];
    const float* v    = (const float*)d_in[8];
    float* out = (float*)d_out;

    starts_kernel<<<(NTOT + 255) / 256, 256>>>(segi);
    ew1_kernel<<<dim3((NENT + BM - 1) / BM, H / BN), 256>>>(ent, W);
    aq_kernel<<<dim3(BQ / QBM, H / QBN), 256>>>(s, r, ent, rel, W, b);
    scoreagg_kernel<<<BQ, 256>>>(s, r, nbr, ent, rel, v, out);
}

// round 8
// speedup vs baseline: 1.2560x; 1.0882x over previous
#include <cuda_runtime.h>

#define H     256
#define SEQL  10
#define BQ    2048
#define NTOT  327680
#define NSEG  (BQ * SEQL)  // 20480
#define NENT  20000

// ---------------- scratch (no cudaMalloc allowed) ----------------
__device__ float g_EW1[NENT * H];      // ent_embeds @ W1   (20.5 MB)
__device__ float g_A[BQ * H];          // s@W2 + r@W3 + b   (2 MB)
__device__ float g_scores[NTOT];       // spill store for huge queries (rare)
__device__ int   g_starts[NSEG + 1];   // segment start offsets

// Packed fp32x2 FMA (Blackwell): two fp32 FMAs per instruction.
__device__ __forceinline__ float2 ffma2(float2 a, float2 b, float2 c) {
    float2 d;
    asm("fma.rn.f32x2 %0, %1, %2, %3;"
        : "=l"(reinterpret_cast<unsigned long long&>(d))
        : "l"(reinterpret_cast<const unsigned long long&>(a)),
          "l"(reinterpret_cast<const unsigned long long&>(b)),
          "l"(reinterpret_cast<const unsigned long long&>(c)));
    return d;
}

__device__ __forceinline__ float tanh_fast(float x) {
    float y;
    asm("tanh.approx.f32 %0, %1;" : "=f"(y) : "f"(x));
    return y;
}

__device__ __forceinline__ float2 f2lo(float4 v) { return make_float2(v.x, v.y); }
__device__ __forceinline__ float2 f2hi(float4 v) { return make_float2(v.z, v.w); }

// ===========================================================================
// Kernel 1: EW1 = ent_embeds @ W1 (rows 0..255 of W).
// BM=64 x BN=128 x BK=16, 256 threads, register-prefetch double buffering.
// ===========================================================================
#define BM 64
#define BN 128
#define BK 16
#define SAW (BK / 2 + 1)   // 9 float4 per sA row

__global__ void __launch_bounds__(256, 3)
ew1_kernel(const float* __restrict__ ent, const float* __restrict__ W) {
    __shared__ float4 sA[BM * SAW];       // 9 KB
    __shared__ float4 sW[BK * (BN / 4)];  // 8 KB
    const int tid   = threadIdx.x;
    const int tm    = tid >> 4;
    const int tn    = tid & 15;
    const int eBase = blockIdx.x * BM;
    const int nBase = blockIdx.y * BN;

    const int se  = tid >> 2;
    const int sk4 = tid & 3;
    const int swk = tid >> 4;
    const int swc = tid & 15;
    const int aRow = min(eBase + se, NENT - 1);

    float2 acc[4][4];
#pragma unroll
    for (int e = 0; e < 4; e++)
#pragma unroll
        for (int j = 0; j < 4; j++) acc[e][j] = make_float2(0.f, 0.f);

    float4 pa  = *reinterpret_cast<const float4*>(ent + (size_t)aRow * H + sk4 * 4);
    float4 pw0 = *(reinterpret_cast<const float4*>(W + (size_t)swk * H + nBase) + swc);
    float4 pw1 = *(reinterpret_cast<const float4*>(W + (size_t)swk * H + nBase) + 16 + swc);

#pragma unroll 1
    for (int kc = 0; kc < H; kc += BK) {
        if (kc) __syncthreads();
        sA[se * SAW + sk4 * 2 + 0] = make_float4(pa.x, pa.x, pa.y, pa.y);
        sA[se * SAW + sk4 * 2 + 1] = make_float4(pa.z, pa.z, pa.w, pa.w);
        sW[swk * (BN / 4) + swc]      = pw0;
        sW[swk * (BN / 4) + 16 + swc] = pw1;
        __syncthreads();

        if (kc + BK < H) {
            pa  = *reinterpret_cast<const float4*>(
                      ent + (size_t)aRow * H + (kc + BK) + sk4 * 4);
            pw0 = *(reinterpret_cast<const float4*>(
                      W + (size_t)(kc + BK + swk) * H + nBase) + swc);
            pw1 = *(reinterpret_cast<const float4*>(
                      W + (size_t)(kc + BK + swk) * H + nBase) + 16 + swc);
        }

#pragma unroll
        for (int k2 = 0; k2 < BK / 2; k2++) {
            const float4 wA0 = sW[(2 * k2) * (BN / 4) + tn];
            const float4 wB0 = sW[(2 * k2) * (BN / 4) + 16 + tn];
            const float4 wA1 = sW[(2 * k2 + 1) * (BN / 4) + tn];
            const float4 wB1 = sW[(2 * k2 + 1) * (BN / 4) + 16 + tn];
#pragma unroll
            for (int e = 0; e < 4; e++) {
                const float4 a = sA[(tm * 4 + e) * SAW + k2];
                const float2 a0 = f2lo(a), a1 = f2hi(a);
                acc[e][0] = ffma2(a0, f2lo(wA0), acc[e][0]);
                acc[e][1] = ffma2(a0, f2hi(wA0), acc[e][1]);
                acc[e][2] = ffma2(a0, f2lo(wB0), acc[e][2]);
                acc[e][3] = ffma2(a0, f2hi(wB0), acc[e][3]);
                acc[e][0] = ffma2(a1, f2lo(wA1), acc[e][0]);
                acc[e][1] = ffma2(a1, f2hi(wA1), acc[e][1]);
                acc[e][2] = ffma2(a1, f2lo(wB1), acc[e][2]);
                acc[e][3] = ffma2(a1, f2hi(wB1), acc[e][3]);
            }
        }
    }

#pragma unroll
    for (int e = 0; e < 4; e++) {
        const int ei = eBase + tm * 4 + e;
        if (ei < NENT) {
            float* row = g_EW1 + (size_t)ei * H + nBase;
            *reinterpret_cast<float4*>(row + tn * 4) =
                make_float4(acc[e][0].x, acc[e][0].y, acc[e][1].x, acc[e][1].y);
            *reinterpret_cast<float4*>(row + 64 + tn * 4) =
                make_float4(acc[e][2].x, acc[e][2].y, acc[e][3].x, acc[e][3].y);
        }
    }
}

// ===========================================================================
// Kernel 2: A = [s_emb | r_emb] @ W[256:768] + b.  64x64 tiles -> 128 blocks.
// ===========================================================================
#define QBM 64
#define QBN 64
__global__ void __launch_bounds__(256)
aq_kernel(const int* __restrict__ s, const int* __restrict__ r,
          const float* __restrict__ ent, const float* __restrict__ rel,
          const float* __restrict__ W, const float* __restrict__ b) {
    __shared__ float4 sA[QBM * SAW];
    __shared__ float4 sW[BK * (QBN / 4)];
    __shared__ int sidx[QBM], ridx[QBM];
    const int tid   = threadIdx.x;
    const int tm    = tid >> 4;
    const int tn    = tid & 15;
    const int qBase = blockIdx.x * QBM;
    const int nBase = blockIdx.y * QBN;

    if (tid < QBM) { sidx[tid] = s[qBase + tid]; ridx[tid] = r[qBase + tid]; }
    __syncthreads();

    float2 acc[4][2];
#pragma unroll
    for (int e = 0; e < 4; e++) {
        acc[e][0] = make_float2(0.f, 0.f);
        acc[e][1] = make_float2(0.f, 0.f);
    }

#pragma unroll 1
    for (int kc = 0; kc < 2 * H; kc += BK) {
        __syncthreads();
        {
            const int e  = tid >> 2;
            const int k4 = tid & 3;
            const float* src = (kc < H)
                ? ent + (size_t)sidx[e] * H + kc
                : rel + (size_t)ridx[e] * H + (kc - H);
            const float4 v = *reinterpret_cast<const float4*>(src + k4 * 4);
            sA[e * SAW + k4 * 2 + 0] = make_float4(v.x, v.x, v.y, v.y);
            sA[e * SAW + k4 * 2 + 1] = make_float4(v.z, v.z, v.w, v.w);
        }
        {
            const int kk = tid >> 4;
            const int c4 = tid & 15;
            sW[kk * (QBN / 4) + c4] = *(reinterpret_cast<const float4*>(
                W + (size_t)(H + kc + kk) * H + nBase) + c4);
        }
        __syncthreads();

#pragma unroll
        for (int k2 = 0; k2 < BK / 2; k2++) {
            const float4 w0 = sW[(2 * k2) * (QBN / 4) + tn];
            const float4 w1 = sW[(2 * k2 + 1) * (QBN / 4) + tn];
#pragma unroll
            for (int e = 0; e < 4; e++) {
                const float4 a = sA[(tm * 4 + e) * SAW + k2];
                acc[e][0] = ffma2(f2lo(a), f2lo(w0), acc[e][0]);
                acc[e][1] = ffma2(f2lo(a), f2hi(w0), acc[e][1]);
                acc[e][0] = ffma2(f2hi(a), f2lo(w1), acc[e][0]);
                acc[e][1] = ffma2(f2hi(a), f2hi(w1), acc[e][1]);
            }
        }
    }

    const float4 b4 = *reinterpret_cast<const float4*>(b + nBase + tn * 4);
#pragma unroll
    for (int e = 0; e < 4; e++) {
        float* row = g_A + (size_t)(qBase + tm * 4 + e) * H + nBase;
        *reinterpret_cast<float4*>(row + tn * 4) =
            make_float4(acc[e][0].x + b4.x, acc[e][0].y + b4.y,
                        acc[e][1].x + b4.z, acc[e][1].y + b4.w);
    }
}

// ---------------------------------------------------------------------------
// Kernel 3: segment start offsets from sorted seg_ids.
// ---------------------------------------------------------------------------
__global__ void starts_kernel(const int* __restrict__ seg_ids) {
    const int i = blockIdx.x * blockDim.x + threadIdx.x;
    if (i >= NTOT) return;
    const int cur  = seg_ids[i];
    const int prev = (i == 0) ? -1 : seg_ids[i - 1];
    for (int sg = prev + 1; sg <= cur; sg++) g_starts[sg] = i;
    if (i == NTOT - 1)
        for (int sg = cur + 1; sg <= NSEG; sg++) g_starts[sg] = NTOT;
}

// ---------------------------------------------------------------------------
// Kernel 4 (FUSED, QUERY-PER-BLOCK): block = one query (10 segments,
// ~160 neighbors). 256 threads.
//  Pass 1: 8 warps, 2 neighbors per iteration (pipelined shfl trees);
//          exp(score) -> smem. No max pass (|score| <= sum|v| ~ 10).
//  Mid:    10 per-segment exp-sums via tiny warp reductions.
//  Pass 2: float2 grain. g = tid>>7 takes neighbors of parity g; h2 = tid&127
//          owns one h-pair. Groups combine via smem once per segment.
// Queries with > QCAP neighbors spill exp-scores via g_scores (correct, rare).
// ---------------------------------------------------------------------------
#define QCAP 512
__global__ void __launch_bounds__(256)
scoreagg_kernel(const int* __restrict__ s, const int* __restrict__ r,
                const int* __restrict__ nbr_ids,
                const float* __restrict__ ent,
                const float* __restrict__ rel,
                const float* __restrict__ v,
                float* __restrict__ out) {
    const int q    = blockIdx.x;
    const int tid  = threadIdx.x;
    const int w    = tid >> 5;
    const int lane = tid & 31;

    __shared__ int    sbnd[SEQL + 1];
    __shared__ float  wsm[QCAP];
    __shared__ int    nsm[QCAP];
    __shared__ float  sdsum[SEQL];
    __shared__ float2 sacc[128];

    if (tid <= SEQL) sbnd[tid] = g_starts[q * SEQL + tid];
    __syncthreads();
    const int qlo  = sbnd[0];
    const int qhi  = sbnd[SEQL];
    const int qcnt = qhi - qlo;

    // ---- pass 1: scores, 2 neighbors per warp-iteration ----
    if (qcnt > 0) {
        const float4* aq = reinterpret_cast<const float4*>(g_A + (size_t)q * H);
        const float4* vv = reinterpret_cast<const float4*>(v);
        const float4 a0 = aq[lane], a1 = aq[lane + 32];
        const float4 v0 = vv[lane], v1 = vv[lane + 32];

        for (int j0 = qlo + w; j0 < qhi; j0 += 16) {
            const int j1   = j0 + 8;
            const bool h1  = (j1 < qhi);
            const int n0   = nbr_ids[j0];
            const int n1   = nbr_ids[h1 ? j1 : j0];

            const float4* ewp0 = reinterpret_cast<const float4*>(
                                     g_EW1 + (size_t)n0 * H);
            const float4* ewp1 = reinterpret_cast<const float4*>(
                                     g_EW1 + (size_t)n1 * H);
            const float4 p0 = ewp0[lane], p1 = ewp0[lane + 32];
            const float4 r0 = ewp1[lane], r1 = ewp1[lane + 32];

            float sc0, sc1;
            sc0 = tanh_fast(p0.x + a0.x) * v0.x;
            sc1 = tanh_fast(r0.x + a0.x) * v0.x;
            sc0 = fmaf(tanh_fast(p0.y + a0.y), v0.y, sc0);
            sc1 = fmaf(tanh_fast(r0.y + a0.y), v0.y, sc1);
            sc0 = fmaf(tanh_fast(p0.z + a0.z), v0.z, sc0);
            sc1 = fmaf(tanh_fast(r0.z + a0.z), v0.z, sc1);
            sc0 = fmaf(tanh_fast(p0.w + a0.w), v0.w, sc0);
            sc1 = fmaf(tanh_fast(r0.w + a0.w), v0.w, sc1);
            sc0 = fmaf(tanh_fast(p1.x + a1.x), v1.x, sc0);
            sc1 = fmaf(tanh_fast(r1.x + a1.x), v1.x, sc1);
            sc0 = fmaf(tanh_fast(p1.y + a1.y), v1.y, sc0);
            sc1 = fmaf(tanh_fast(r1.y + a1.y), v1.y, sc1);
            sc0 = fmaf(tanh_fast(p1.z + a1.z), v1.z, sc0);
            sc1 = fmaf(tanh_fast(r1.z + a1.z), v1.z, sc1);
            sc0 = fmaf(tanh_fast(p1.w + a1.w), v1.w, sc0);
            sc1 = fmaf(tanh_fast(r1.w + a1.w), v1.w, sc1);
#pragma unroll
            for (int o = 16; o; o >>= 1) {
                sc0 += __shfl_xor_sync(0xffffffffu, sc0, o);
                sc1 += __shfl_xor_sync(0xffffffffu, sc1, o);
            }
            if (lane == 0) {
                const float e0 = __expf(sc0);
                const int k0 = j0 - qlo;
                if (k0 < QCAP) { wsm[k0] = e0; nsm[k0] = n0; }
                else           g_scores[j0] = e0;
                if (h1) {
                    const float e1 = __expf(sc1);
                    const int k1 = j1 - qlo;
                    if (k1 < QCAP) { wsm[k1] = e1; nsm[k1] = n1; }
                    else           g_scores[j1] = e1;
                }
            }
        }
    }
    __syncthreads();

    // ---- per-segment exp sums (segment sizes ~16) ----
    for (int t = w; t < SEQL; t += 8) {
        const int slo = sbnd[t]     - qlo;
        const int shi = sbnd[t + 1] - qlo;
        float d = 0.0f;
        for (int k = slo + lane; k < shi; k += 32)
            d += (k < QCAP) ? wsm[k] : g_scores[qlo + k];
#pragma unroll
        for (int o = 16; o; o >>= 1) d += __shfl_xor_sync(0xffffffffu, d, o);
        if (lane == 0) sdsum[t] = d;
    }

    // ---- pass 2 setup: float2 grain ----
    const int g  = tid >> 7;                 // parity group 0/1
    const int h2 = tid & 127;                // h-pair index
    // group 0 writes agg + s_emb halves; group 1 writes r_emb half.
    const float2 sr2 = (g == 0)
        ? *reinterpret_cast<const float2*>(ent + (size_t)s[q] * H + 2 * h2)
        : *reinterpret_cast<const float2*>(rel + (size_t)r[q] * H + 2 * h2);
    __syncthreads();

    float* qout = out + (size_t)q * SEQL * (3 * H);
#pragma unroll 1
    for (int t = 0; t < SEQL; t++) {
        float* row = qout + (size_t)t * (3 * H);
        float2* rowA = reinterpret_cast<float2*>(row);          // agg
        float2* rowS = reinterpret_cast<float2*>(row + H);      // s_emb
        float2* rowR = reinterpret_cast<float2*>(row + 2 * H);  // r_emb
        const int slo = sbnd[t]     - qlo;
        const int shi = sbnd[t + 1] - qlo;

        if (slo >= shi) {
            if (g == 0) { rowA[h2] = make_float2(0.f, 0.f);
                          rowS[h2] = make_float2(0.f, 0.f); }
            else          rowR[h2] = make_float2(0.f, 0.f);
            continue;
        }
        const float inv = 1.0f / sdsum[t];
        const int c = min(shi, QCAP);

        float2 a0 = make_float2(0.f, 0.f), a1 = make_float2(0.f, 0.f);
        float2 a2 = make_float2(0.f, 0.f), a3 = make_float2(0.f, 0.f);
        int k = slo + g;
        for (; k + 6 < c; k += 8) {
            const float w0 = wsm[k],     w1 = wsm[k + 2];
            const float w2 = wsm[k + 4], w3 = wsm[k + 6];
            const float2 e0 = *reinterpret_cast<const float2*>(
                                  ent + (size_t)nsm[k] * H + 2 * h2);
            const float2 e1 = *reinterpret_cast<const float2*>(
                                  ent + (size_t)nsm[k + 2] * H + 2 * h2);
            const float2 e2 = *reinterpret_cast<const float2*>(
                                  ent + (size_t)nsm[k + 4] * H + 2 * h2);
            const float2 e3 = *reinterpret_cast<const float2*>(
                                  ent + (size_t)nsm[k + 6] * H + 2 * h2);
            a0.x = fmaf(w0, e0.x, a0.x); a0.y = fmaf(w0, e0.y, a0.y);
            a1.x = fmaf(w1, e1.x, a1.x); a1.y = fmaf(w1, e1.y, a1.y);
            a2.x = fmaf(w2, e2.x, a2.x); a2.y = fmaf(w2, e2.y, a2.y);
            a3.x = fmaf(w3, e3.x, a3.x); a3.y = fmaf(w3, e3.y, a3.y);
        }
        for (; k < c; k += 2) {
            const float w0 = wsm[k];
            const float2 e0 = *reinterpret_cast<const float2*>(
                                  ent + (size_t)nsm[k] * H + 2 * h2);
            a0.x = fmaf(w0, e0.x, a0.x); a0.y = fmaf(w0, e0.y, a0.y);
        }
        for (; k < shi; k += 2) {                     // spill path (rare)
            const float w0 = g_scores[qlo + k];
            const float2 e0 = *reinterpret_cast<const float2*>(
                                  ent + (size_t)nbr_ids[qlo + k] * H + 2 * h2);
            a0.x = fmaf(w0, e0.x, a0.x); a0.y = fmaf(w0, e0.y, a0.y);
        }
        float2 acc = make_float2((a0.x + a1.x) + (a2.x + a3.x),
                                 (a0.y + a1.y) + (a2.y + a3.y));

        if (g == 1) sacc[h2] = acc;
        __syncthreads();
        if (g == 0) {
            const float2 other = sacc[h2];
            rowA[h2] = make_float2((acc.x + other.x) * inv,
                                   (acc.y + other.y) * inv);
            rowS[h2] = sr2;
        } else {
            rowR[h2] = sr2;
        }
        __syncthreads();
    }
}

// ---------------------------------------------------------------------------
extern "C" void kernel_launch(void* const* d_in, const int* in_sizes, int n_in,
                              void* d_out, int out_size) {
    const int*   s    = (const int*)d_in[0];
    const int*   r    = (const int*)d_in[1];
    const int*   nbr  = (const int*)d_in[2];
    const int*   segi = (const int*)d_in[3];
    const float* ent  = (const float*)d_in[4];
    const float* rel  = (const float*)d_in[5];
    const float* W    = (const float*)d_in[6];
    const float* b    = (const float*)d_in[7];
    const float* v    = (const float*)d_in[8];
    float* out = (float*)d_out;

    starts_kernel<<<(NTOT + 255) / 256, 256>>>(segi);
    ew1_kernel<<<dim3((NENT + BM - 1) / BM, H / BN), 256>>>(ent, W);
    aq_kernel<<<dim3(BQ / QBM, H / QBN), 256>>>(s, r, ent, rel, W, b);
    scoreagg_kernel<<<BQ, 256>>>(s, r, nbr, ent, rel, v, out);
}

// round 9
// speedup vs baseline: 1.3369x; 1.0644x over previous
#include <cuda_runtime.h>

#define H     256
#define SEQL  10
#define BQ    2048
#define NTOT  327680
#define NSEG  (BQ * SEQL)  // 20480
#define NENT  20000

// ---------------- scratch (no cudaMalloc allowed) ----------------
__device__ float g_EW1[NENT * H];      // ent_embeds @ W1   (20.5 MB)
__device__ float g_A[BQ * H];          // s@W2 + r@W3 + b   (2 MB)
__device__ float g_scores[NTOT];       // spill store for huge queries (rare)
__device__ int   g_starts[NSEG + 1];   // segment start offsets

// Packed fp32x2 FMA (Blackwell): two fp32 FMAs per instruction.
__device__ __forceinline__ float2 ffma2(float2 a, float2 b, float2 c) {
    float2 d;
    asm("fma.rn.f32x2 %0, %1, %2, %3;"
        : "=l"(reinterpret_cast<unsigned long long&>(d))
        : "l"(reinterpret_cast<const unsigned long long&>(a)),
          "l"(reinterpret_cast<const unsigned long long&>(b)),
          "l"(reinterpret_cast<const unsigned long long&>(c)));
    return d;
}

__device__ __forceinline__ float tanh_fast(float x) {
    float y;
    asm("tanh.approx.f32 %0, %1;" : "=f"(y) : "f"(x));
    return y;
}

__device__ __forceinline__ float2 f2lo(float4 v) { return make_float2(v.x, v.y); }
__device__ __forceinline__ float2 f2hi(float4 v) { return make_float2(v.z, v.w); }

// ===========================================================================
// Kernel 1: EW1 = ent_embeds @ W1 (rows 0..255 of W).
// BM=64 x BN=128 x BK=32, 256 threads, 8 chunks, register-prefetch double
// buffering. smem = 17.4 + 16 KB = 33.8 KB static.
// ===========================================================================
#define BM 64
#define BN 128
#define BK 32
#define SAW (BK / 2 + 1)   // 17 float4 per sA row

__global__ void __launch_bounds__(256, 3)
ew1_kernel(const float* __restrict__ ent, const float* __restrict__ W) {
    __shared__ float4 sA[BM * SAW];       // 17.4 KB (dup-pairs, padded)
    __shared__ float4 sW[BK * (BN / 4)];  // 16 KB
    const int tid   = threadIdx.x;
    const int tm    = tid >> 4;            // 0..15 (4 rows each)
    const int tn    = tid & 15;            // 0..15 (8 cols, split 2x4)
    const int eBase = blockIdx.x * BM;
    const int nBase = blockIdx.y * BN;

    // staging indices: A 512 f4 (2/thread), W 1024 f4 (4/thread)
    const int e0  = tid >> 3;              // 0..31 (rows e0, e0+32)
    const int k4  = tid & 7;               // f4-within-row
    const int swk = tid >> 5;              // 0..7  (W rows swk + 8i)
    const int swc = tid & 31;              // W col f4
    const int row0 = min(eBase + e0,      NENT - 1);
    const int row1 = min(eBase + e0 + 32, NENT - 1);

    float2 acc[4][4];
#pragma unroll
    for (int e = 0; e < 4; e++)
#pragma unroll
        for (int j = 0; j < 4; j++) acc[e][j] = make_float2(0.f, 0.f);

    // prefetch chunk 0
    float4 pa0 = *reinterpret_cast<const float4*>(ent + (size_t)row0 * H + k4 * 4);
    float4 pa1 = *reinterpret_cast<const float4*>(ent + (size_t)row1 * H + k4 * 4);
    float4 pw[4];
#pragma unroll
    for (int i = 0; i < 4; i++)
        pw[i] = *(reinterpret_cast<const float4*>(
                      W + (size_t)(swk + 8 * i) * H + nBase) + swc);

#pragma unroll 1
    for (int kc = 0; kc < H; kc += BK) {
        if (kc) __syncthreads();
        sA[e0 * SAW + k4 * 2 + 0]        = make_float4(pa0.x, pa0.x, pa0.y, pa0.y);
        sA[e0 * SAW + k4 * 2 + 1]        = make_float4(pa0.z, pa0.z, pa0.w, pa0.w);
        sA[(e0 + 32) * SAW + k4 * 2 + 0] = make_float4(pa1.x, pa1.x, pa1.y, pa1.y);
        sA[(e0 + 32) * SAW + k4 * 2 + 1] = make_float4(pa1.z, pa1.z, pa1.w, pa1.w);
#pragma unroll
        for (int i = 0; i < 4; i++)
            sW[(swk + 8 * i) * (BN / 4) + swc] = pw[i];
        __syncthreads();

        if (kc + BK < H) {                 // prefetch next chunk under compute
            pa0 = *reinterpret_cast<const float4*>(
                      ent + (size_t)row0 * H + (kc + BK) + k4 * 4);
            pa1 = *reinterpret_cast<const float4*>(
                      ent + (size_t)row1 * H + (kc + BK) + k4 * 4);
#pragma unroll
            for (int i = 0; i < 4; i++)
                pw[i] = *(reinterpret_cast<const float4*>(
                              W + (size_t)(kc + BK + swk + 8 * i) * H + nBase) + swc);
        }

#pragma unroll
        for (int k2 = 0; k2 < BK / 2; k2++) {
            const float4 wA0 = sW[(2 * k2) * (BN / 4) + tn];
            const float4 wB0 = sW[(2 * k2) * (BN / 4) + 16 + tn];
            const float4 wA1 = sW[(2 * k2 + 1) * (BN / 4) + tn];
            const float4 wB1 = sW[(2 * k2 + 1) * (BN / 4) + 16 + tn];
#pragma unroll
            for (int e = 0; e < 4; e++) {
                const float4 a = sA[(tm * 4 + e) * SAW + k2];   // {ak,ak,ak1,ak1}
                const float2 a0 = f2lo(a), a1 = f2hi(a);
                acc[e][0] = ffma2(a0, f2lo(wA0), acc[e][0]);
                acc[e][1] = ffma2(a0, f2hi(wA0), acc[e][1]);
                acc[e][2] = ffma2(a0, f2lo(wB0), acc[e][2]);
                acc[e][3] = ffma2(a0, f2hi(wB0), acc[e][3]);
                acc[e][0] = ffma2(a1, f2lo(wA1), acc[e][0]);
                acc[e][1] = ffma2(a1, f2hi(wA1), acc[e][1]);
                acc[e][2] = ffma2(a1, f2lo(wB1), acc[e][2]);
                acc[e][3] = ffma2(a1, f2hi(wB1), acc[e][3]);
            }
        }
    }

#pragma unroll
    for (int e = 0; e < 4; e++) {
        const int ei = eBase + tm * 4 + e;
        if (ei < NENT) {
            float* row = g_EW1 + (size_t)ei * H + nBase;
            *reinterpret_cast<float4*>(row + tn * 4) =
                make_float4(acc[e][0].x, acc[e][0].y, acc[e][1].x, acc[e][1].y);
            *reinterpret_cast<float4*>(row + 64 + tn * 4) =
                make_float4(acc[e][2].x, acc[e][2].y, acc[e][3].x, acc[e][3].y);
        }
    }
}

// ===========================================================================
// Kernel 2: A = [s_emb | r_emb] @ W[256:768] + b.  64x64 tiles, 128 blocks,
// BK=32 (16 chunks), register-prefetch double buffering.
// ===========================================================================
#define QBM 64
#define QBN 64
__global__ void __launch_bounds__(256)
aq_kernel(const int* __restrict__ s, const int* __restrict__ r,
          const float* __restrict__ ent, const float* __restrict__ rel,
          const float* __restrict__ W, const float* __restrict__ b) {
    __shared__ float4 sA[QBM * SAW];       // 17.4 KB
    __shared__ float4 sW[BK * (QBN / 4)];  // 8 KB
    __shared__ int sidx[QBM], ridx[QBM];
    const int tid   = threadIdx.x;
    const int tm    = tid >> 4;
    const int tn    = tid & 15;
    const int qBase = blockIdx.x * QBM;
    const int nBase = blockIdx.y * QBN;

    if (tid < QBM) { sidx[tid] = s[qBase + tid]; ridx[tid] = r[qBase + tid]; }
    __syncthreads();

    // staging indices: A 512 f4 (2/thread), W 512 f4 (2/thread)
    const int e0  = tid >> 3;              // rows e0, e0+32
    const int k4  = tid & 7;
    const int swk = tid >> 4;              // W rows swk, swk+16
    const int swc = tid & 15;

    float2 acc[4][2];
#pragma unroll
    for (int e = 0; e < 4; e++) {
        acc[e][0] = make_float2(0.f, 0.f);
        acc[e][1] = make_float2(0.f, 0.f);
    }

    // A-row source for a given chunk base
    auto aSrc = [&](int kc, int e) -> const float* {
        return (kc < H) ? ent + (size_t)sidx[e] * H + kc
                        : rel + (size_t)ridx[e] * H + (kc - H);
    };

    // prefetch chunk 0
    float4 pa0 = *reinterpret_cast<const float4*>(aSrc(0, e0)      + k4 * 4);
    float4 pa1 = *reinterpret_cast<const float4*>(aSrc(0, e0 + 32) + k4 * 4);
    float4 pw0 = *(reinterpret_cast<const float4*>(
                       W + (size_t)(H + swk) * H + nBase) + swc);
    float4 pw1 = *(reinterpret_cast<const float4*>(
                       W + (size_t)(H + swk + 16) * H + nBase) + swc);

#pragma unroll 1
    for (int kc = 0; kc < 2 * H; kc += BK) {
        if (kc) __syncthreads();
        sA[e0 * SAW + k4 * 2 + 0]        = make_float4(pa0.x, pa0.x, pa0.y, pa0.y);
        sA[e0 * SAW + k4 * 2 + 1]        = make_float4(pa0.z, pa0.z, pa0.w, pa0.w);
        sA[(e0 + 32) * SAW + k4 * 2 + 0] = make_float4(pa1.x, pa1.x, pa1.y, pa1.y);
        sA[(e0 + 32) * SAW + k4 * 2 + 1] = make_float4(pa1.z, pa1.z, pa1.w, pa1.w);
        sW[swk * (QBN / 4) + swc]        = pw0;
        sW[(swk + 16) * (QBN / 4) + swc] = pw1;
        __syncthreads();

        if (kc + BK < 2 * H) {
            const int kn = kc + BK;
            pa0 = *reinterpret_cast<const float4*>(aSrc(kn, e0)      + k4 * 4);
            pa1 = *reinterpret_cast<const float4*>(aSrc(kn, e0 + 32) + k4 * 4);
            pw0 = *(reinterpret_cast<const float4*>(
                        W + (size_t)(H + kn + swk) * H + nBase) + swc);
            pw1 = *(reinterpret_cast<const float4*>(
                        W + (size_t)(H + kn + swk + 16) * H + nBase) + swc);
        }

#pragma unroll
        for (int k2 = 0; k2 < BK / 2; k2++) {
            const float4 w0 = sW[(2 * k2) * (QBN / 4) + tn];
            const float4 w1 = sW[(2 * k2 + 1) * (QBN / 4) + tn];
#pragma unroll
            for (int e = 0; e < 4; e++) {
                const float4 a = sA[(tm * 4 + e) * SAW + k2];
                acc[e][0] = ffma2(f2lo(a), f2lo(w0), acc[e][0]);
                acc[e][1] = ffma2(f2lo(a), f2hi(w0), acc[e][1]);
                acc[e][0] = ffma2(f2hi(a), f2lo(w1), acc[e][0]);
                acc[e][1] = ffma2(f2hi(a), f2hi(w1), acc[e][1]);
            }
        }
    }

    const float4 b4 = *reinterpret_cast<const float4*>(b + nBase + tn * 4);
#pragma unroll
    for (int e = 0; e < 4; e++) {
        float* row = g_A + (size_t)(qBase + tm * 4 + e) * H + nBase;
        *reinterpret_cast<float4*>(row + tn * 4) =
            make_float4(acc[e][0].x + b4.x, acc[e][0].y + b4.y,
                        acc[e][1].x + b4.z, acc[e][1].y + b4.w);
    }
}

// ---------------------------------------------------------------------------
// Kernel 3: segment start offsets from sorted seg_ids.
// ---------------------------------------------------------------------------
__global__ void starts_kernel(const int* __restrict__ seg_ids) {
    const int i = blockIdx.x * blockDim.x + threadIdx.x;
    if (i >= NTOT) return;
    const int cur  = seg_ids[i];
    const int prev = (i == 0) ? -1 : seg_ids[i - 1];
    for (int sg = prev + 1; sg <= cur; sg++) g_starts[sg] = i;
    if (i == NTOT - 1)
        for (int sg = cur + 1; sg <= NSEG; sg++) g_starts[sg] = NTOT;
}

// ---------------------------------------------------------------------------
// Kernel 4 (FUSED, QUERY-PER-BLOCK): block = one query (10 segments,
// ~160 neighbors). 256 threads.
//  Pass 1: 8 warps, 2 neighbors per iteration (pipelined shfl trees);
//          exp(score) -> smem. No max pass (|score| <= sum|v| ~ 10).
//  Mid:    10 per-segment exp-sums via tiny warp reductions.
//  Pass 2: group g = tid>>7 owns segments {g, g+2, ...}; 128 threads gather
//          full rows at float2 grain. No cross-group combine, NO syncs.
// Queries with > QCAP neighbors spill exp-scores via g_scores (correct, rare).
// ---------------------------------------------------------------------------
#define QCAP 512
__global__ void __launch_bounds__(256)
scoreagg_kernel(const int* __restrict__ s, const int* __restrict__ r,
                const int* __restrict__ nbr_ids,
                const float* __restrict__ ent,
                const float* __restrict__ rel,
                const float* __restrict__ v,
                float* __restrict__ out) {
    const int q    = blockIdx.x;
    const int tid  = threadIdx.x;
    const int w    = tid >> 5;
    const int lane = tid & 31;

    __shared__ int    sbnd[SEQL + 1];
    __shared__ float  wsm[QCAP];
    __shared__ int    nsm[QCAP];
    __shared__ float  sdsum[SEQL];

    if (tid <= SEQL) sbnd[tid] = g_starts[q * SEQL + tid];
    __syncthreads();
    const int qlo  = sbnd[0];
    const int qhi  = sbnd[SEQL];
    const int qcnt = qhi - qlo;

    // ---- pass 1: scores, 2 neighbors per warp-iteration ----
    if (qcnt > 0) {
        const float4* aq = reinterpret_cast<const float4*>(g_A + (size_t)q * H);
        const float4* vv = reinterpret_cast<const float4*>(v);
        const float4 a0 = aq[lane], a1 = aq[lane + 32];
        const float4 v0 = vv[lane], v1 = vv[lane + 32];

        for (int j0 = qlo + w; j0 < qhi; j0 += 16) {
            const int j1   = j0 + 8;
            const bool h1  = (j1 < qhi);
            const int n0   = nbr_ids[j0];
            const int n1   = nbr_ids[h1 ? j1 : j0];

            const float4* ewp0 = reinterpret_cast<const float4*>(
                                     g_EW1 + (size_t)n0 * H);
            const float4* ewp1 = reinterpret_cast<const float4*>(
                                     g_EW1 + (size_t)n1 * H);
            const float4 p0 = ewp0[lane], p1 = ewp0[lane + 32];
            const float4 r0 = ewp1[lane], r1 = ewp1[lane + 32];

            float sc0, sc1;
            sc0 = tanh_fast(p0.x + a0.x) * v0.x;
            sc1 = tanh_fast(r0.x + a0.x) * v0.x;
            sc0 = fmaf(tanh_fast(p0.y + a0.y), v0.y, sc0);
            sc1 = fmaf(tanh_fast(r0.y + a0.y), v0.y, sc1);
            sc0 = fmaf(tanh_fast(p0.z + a0.z), v0.z, sc0);
            sc1 = fmaf(tanh_fast(r0.z + a0.z), v0.z, sc1);
            sc0 = fmaf(tanh_fast(p0.w + a0.w), v0.w, sc0);
            sc1 = fmaf(tanh_fast(r0.w + a0.w), v0.w, sc1);
            sc0 = fmaf(tanh_fast(p1.x + a1.x), v1.x, sc0);
            sc1 = fmaf(tanh_fast(r1.x + a1.x), v1.x, sc1);
            sc0 = fmaf(tanh_fast(p1.y + a1.y), v1.y, sc0);
            sc1 = fmaf(tanh_fast(r1.y + a1.y), v1.y, sc1);
            sc0 = fmaf(tanh_fast(p1.z + a1.z), v1.z, sc0);
            sc1 = fmaf(tanh_fast(r1.z + a1.z), v1.z, sc1);
            sc0 = fmaf(tanh_fast(p1.w + a1.w), v1.w, sc0);
            sc1 = fmaf(tanh_fast(r1.w + a1.w), v1.w, sc1);
#pragma unroll
            for (int o = 16; o; o >>= 1) {
                sc0 += __shfl_xor_sync(0xffffffffu, sc0, o);
                sc1 += __shfl_xor_sync(0xffffffffu, sc1, o);
            }
            if (lane == 0) {
                const float e0 = __expf(sc0);
                const int k0 = j0 - qlo;
                if (k0 < QCAP) { wsm[k0] = e0; nsm[k0] = n0; }
                else           g_scores[j0] = e0;
                if (h1) {
                    const float e1 = __expf(sc1);
                    const int k1 = j1 - qlo;
                    if (k1 < QCAP) { wsm[k1] = e1; nsm[k1] = n1; }
                    else           g_scores[j1] = e1;
                }
            }
        }
    }
    __syncthreads();

    // ---- per-segment exp sums (segment sizes ~16) ----
    for (int t = w; t < SEQL; t += 8) {
        const int slo = sbnd[t]     - qlo;
        const int shi = sbnd[t + 1] - qlo;
        float d = 0.0f;
        for (int k = slo + lane; k < shi; k += 32)
            d += (k < QCAP) ? wsm[k] : g_scores[qlo + k];
#pragma unroll
        for (int o = 16; o; o >>= 1) d += __shfl_xor_sync(0xffffffffu, d, o);
        if (lane == 0) sdsum[t] = d;
    }

    // ---- pass 2 setup: group g owns segments {g, g+2, ...} ----
    const int g  = tid >> 7;                 // 0/1
    const int h2 = tid & 127;                // h-pair index
    const float2 s2 = *reinterpret_cast<const float2*>(
                          ent + (size_t)s[q] * H + 2 * h2);
    const float2 r2 = *reinterpret_cast<const float2*>(
                          rel + (size_t)r[q] * H + 2 * h2);
    __syncthreads();                         // wsm/nsm/sdsum ready

    float* qout = out + (size_t)q * SEQL * (3 * H);
#pragma unroll 1
    for (int t = g; t < SEQL; t += 2) {
        float* row = qout + (size_t)t * (3 * H);
        float2* rowA = reinterpret_cast<float2*>(row);          // agg
        float2* rowS = reinterpret_cast<float2*>(row + H);      // s_emb
        float2* rowR = reinterpret_cast<float2*>(row + 2 * H);  // r_emb
        const int slo = sbnd[t]     - qlo;
        const int shi = sbnd[t + 1] - qlo;

        if (slo >= shi) {
            rowA[h2] = make_float2(0.f, 0.f);
            rowS[h2] = make_float2(0.f, 0.f);
            rowR[h2] = make_float2(0.f, 0.f);
            continue;
        }
        const float inv = 1.0f / sdsum[t];
        const int c = min(shi, QCAP);

        float2 a0 = make_float2(0.f, 0.f), a1 = make_float2(0.f, 0.f);
        float2 a2 = make_float2(0.f, 0.f), a3 = make_float2(0.f, 0.f);
        int k = slo;
        for (; k + 3 < c; k += 4) {
            const float w0 = wsm[k],     w1 = wsm[k + 1];
            const float w2 = wsm[k + 2], w3 = wsm[k + 3];
            const float2 e0 = *reinterpret_cast<const float2*>(
                                  ent + (size_t)nsm[k] * H + 2 * h2);
            const float2 e1 = *reinterpret_cast<const float2*>(
                                  ent + (size_t)nsm[k + 1] * H + 2 * h2);
            const float2 e2 = *reinterpret_cast<const float2*>(
                                  ent + (size_t)nsm[k + 2] * H + 2 * h2);
            const float2 e3 = *reinterpret_cast<const float2*>(
                                  ent + (size_t)nsm[k + 3] * H + 2 * h2);
            a0.x = fmaf(w0, e0.x, a0.x); a0.y = fmaf(w0, e0.y, a0.y);
            a1.x = fmaf(w1, e1.x, a1.x); a1.y = fmaf(w1, e1.y, a1.y);
            a2.x = fmaf(w2, e2.x, a2.x); a2.y = fmaf(w2, e2.y, a2.y);
            a3.x = fmaf(w3, e3.x, a3.x); a3.y = fmaf(w3, e3.y, a3.y);
        }
        for (; k < c; k++) {
            const float w0 = wsm[k];
            const float2 e0 = *reinterpret_cast<const float2*>(
                                  ent + (size_t)nsm[k] * H + 2 * h2);
            a0.x = fmaf(w0, e0.x, a0.x); a0.y = fmaf(w0, e0.y, a0.y);
        }
        for (; k < shi; k++) {                        // spill path (rare)
            const float w0 = g_scores[qlo + k];
            const float2 e0 = *reinterpret_cast<const float2*>(
                                  ent + (size_t)nbr_ids[qlo + k] * H + 2 * h2);
            a0.x = fmaf(w0, e0.x, a0.x); a0.y = fmaf(w0, e0.y, a0.y);
        }

        rowA[h2] = make_float2(((a0.x + a1.x) + (a2.x + a3.x)) * inv,
                               ((a0.y + a1.y) + (a2.y + a3.y)) * inv);
        rowS[h2] = s2;
        rowR[h2] = r2;
    }
}

// ---------------------------------------------------------------------------
extern "C" void kernel_launch(void* const* d_in, const int* in_sizes, int n_in,
                              void* d_out, int out_size) {
    const int*   s    = (const int*)d_in[0];
    const int*   r    = (const int*)d_in[1];
    const int*   nbr  = (const int*)d_in[2];
    const int*   segi = (const int*)d_in[3];
    const float* ent  = (const float*)d_in[4];
    const float* rel  = (const float*)d_in[5];
    const float* W    = (const float*)d_in[6];
    const float* b    = (const float*)d_in[7];
    const float* v    = (const float*)d_in[8];
    float* out = (float*)d_out;

    starts_kernel<<<(NTOT + 255) / 256, 256>>>(segi);
    ew1_kernel<<<dim3((NENT + BM - 1) / BM, H / BN), 256>>>(ent, W);
    aq_kernel<<<dim3(BQ / QBM, H / QBN), 256>>>(s, r, ent, rel, W, b);
    scoreagg_kernel<<<BQ, 256>>>(s, r, nbr, ent, rel, v, out);
}

// round 11
// speedup vs baseline: 1.8193x; 1.3608x over previous
#include <cuda_runtime.h>
#include <cuda_bf16.h>
#include <cstdint>

#define H     256
#define SEQL  10
#define BQ    2048
#define NTOT  327680
#define NSEG  (BQ * SEQL)  // 20480
#define NENT  20000

// ---------------- scratch (no cudaMalloc allowed) ----------------
__device__ float g_EW1[NENT * H];      // ent_embeds @ W1   (20.5 MB)
__device__ float g_A[BQ * H];          // s@W2 + r@W3 + b   (2 MB)
__device__ float g_scores[NTOT];       // spill store for huge queries (rare)
__device__ int   g_starts[NSEG + 1];   // segment start offsets
__device__ __nv_bfloat16 g_Wt_hi[H * H];  // W1^T hi (bf16), [n][k]
__device__ __nv_bfloat16 g_Wt_lo[H * H];  // W1^T lo residual

// Packed fp32x2 FMA (Blackwell): two fp32 FMAs per instruction.
__device__ __forceinline__ float2 ffma2(float2 a, float2 b, float2 c) {
    float2 d;
    asm("fma.rn.f32x2 %0, %1, %2, %3;"
        : "=l"(reinterpret_cast<unsigned long long&>(d))
        : "l"(reinterpret_cast<const unsigned long long&>(a)),
          "l"(reinterpret_cast<const unsigned long long&>(b)),
          "l"(reinterpret_cast<const unsigned long long&>(c)));
    return d;
}

__device__ __forceinline__ float tanh_fast(float x) {
    float y;
    asm("tanh.approx.f32 %0, %1;" : "=f"(y) : "f"(x));
    return y;
}

__device__ __forceinline__ float2 f2lo(float4 v) { return make_float2(v.x, v.y); }
__device__ __forceinline__ float2 f2hi(float4 v) { return make_float2(v.z, v.w); }

__device__ __forceinline__ uint32_t smem_u32(const void* p) {
    uint32_t a;
    asm("{ .reg .u64 t; cvta.to.shared.u64 t, %1; cvt.u32.u64 %0, t; }"
        : "=r"(a) : "l"(p));
    return a;
}

__device__ __forceinline__ uint32_t sw128(uint32_t x) {
    return x ^ ((x >> 3) & 0x70);
}

__device__ __forceinline__ void ldsm_x4(uint32_t* r, uint32_t addr) {
    asm volatile("ldmatrix.sync.aligned.m8n8.x4.shared.b16 {%0,%1,%2,%3}, [%4];"
                 : "=r"(r[0]), "=r"(r[1]), "=r"(r[2]), "=r"(r[3]) : "r"(addr));
}

__device__ __forceinline__ void mma_bf16(float* c, const uint32_t* a,
                                         const uint32_t* b) {
    asm volatile(
        "mma.sync.aligned.m16n8k16.row.col.f32.bf16.bf16.f32 "
        "{%0,%1,%2,%3}, {%4,%5,%6,%7}, {%8,%9}, {%0,%1,%2,%3};"
        : "+f"(c[0]), "+f"(c[1]), "+f"(c[2]), "+f"(c[3])
        : "r"(a[0]), "r"(a[1]), "r"(a[2]), "r"(a[3]), "r"(b[0]), "r"(b[1]));
}

// ===========================================================================
// Kernel 0: transpose W1 (rows 0..255 of W) and split to bf16 hi/lo.
// ===========================================================================
__global__ void wsplit_kernel(const float* __restrict__ W) {
    __shared__ float t[32][33];
    const int bx = blockIdx.x & 7;       // k tile
    const int by = blockIdx.x >> 3;      // n tile
    const int tx = threadIdx.x & 31;
    const int ty = threadIdx.x >> 5;     // 0..7
#pragma unroll
    for (int i = 0; i < 4; i++) {
        const int k = bx * 32 + ty + i * 8;
        const int n = by * 32 + tx;
        t[ty + i * 8][tx] = W[k * H + n];
    }
    __syncthreads();
#pragma unroll
    for (int i = 0; i < 4; i++) {
        const int n = by * 32 + ty + i * 8;
        const int k = bx * 32 + tx;
        const float x = t[tx][ty + i * 8];
        const __nv_bfloat16 hi = __float2bfloat16(x);
        const __nv_bfloat16 lo = __float2bfloat16(x - __bfloat162float(hi));
        g_Wt_hi[n * H + k] = hi;
        g_Wt_lo[n * H + k] = lo;
    }
}

// ===========================================================================
// Kernel 1: EW1 = ent @ W1 via mma.sync bf16 (HMMA) + hi/lo compensation.
// D = Ahi@Bhi + Ahi@Blo + Alo@Bhi (fp32 accum).
// Block: 256 threads (8 warps, 4m x 2n), tile M=128 x N=64, K chunks of 64.
// Warp tile 32x32: 2 m16-tiles x 4 n8-tiles. SW128-swizzled smem (128B rows).
// Grid: (ceil(NENT/128), 4).
// ===========================================================================
#define MM_AHI 0
#define MM_ALO 16384
#define MM_BHI 32768
#define MM_BLO 40960
#define MM_SMEM 49152

__global__ void __launch_bounds__(256)
ew1_mma_kernel(const float* __restrict__ ent) {
    extern __shared__ char smem[];
    const uint32_t sb = smem_u32(smem);
    const int tid   = threadIdx.x;
    const int wid   = tid >> 5;
    const int lane  = tid & 31;
    const int wm    = wid & 3;             // warp m index (0..3)
    const int wn    = wid >> 2;            // warp n index (0..1)
    const int eBase = blockIdx.x * 128;
    const int nBase = blockIdx.y * 64;

    // ldmatrix lane mapping
    const int lmat = lane >> 3;            // matrix index 0..3
    const int lrow = lane & 7;             // row within matrix

    float acc[2][4][4];
#pragma unroll
    for (int mt = 0; mt < 2; mt++)
#pragma unroll
        for (int nt = 0; nt < 4; nt++)
#pragma unroll
            for (int j = 0; j < 4; j++) acc[mt][nt][j] = 0.0f;

#pragma unroll 1
    for (int c = 0; c < 4; c++) {
        const int kc = c * 64;
        if (c) __syncthreads();

        // ---- stage A hi/lo: 128 rows x 64 k (fp32 -> bf16 split) ----
        // 2048 float4 -> 8 per thread
#pragma unroll
        for (int it = 0; it < 8; it++) {
            const int idx = tid + it * 256;        // 0..2047
            const int row = idx >> 4;
            const int q4  = idx & 15;
            int er = eBase + row; if (er >= NENT) er = 0;
            const float4 x = *reinterpret_cast<const float4*>(
                                 ent + (size_t)er * H + kc + q4 * 4);
            const __nv_bfloat16 h0 = __float2bfloat16(x.x);
            const __nv_bfloat16 h1 = __float2bfloat16(x.y);
            const __nv_bfloat16 h2 = __float2bfloat16(x.z);
            const __nv_bfloat16 h3 = __float2bfloat16(x.w);
            const __nv_bfloat16 l0 = __float2bfloat16(x.x - __bfloat162float(h0));
            const __nv_bfloat16 l1 = __float2bfloat16(x.y - __bfloat162float(h1));
            const __nv_bfloat16 l2 = __float2bfloat16(x.z - __bfloat162float(h2));
            const __nv_bfloat16 l3 = __float2bfloat16(x.w - __bfloat162float(h3));
            const uint32_t sw = sw128(row * 128 + q4 * 8);
            *reinterpret_cast<__nv_bfloat162*>(smem + MM_AHI + sw)     =
                __halves2bfloat162(h0, h1);
            *reinterpret_cast<__nv_bfloat162*>(smem + MM_AHI + sw + 4) =
                __halves2bfloat162(h2, h3);
            *reinterpret_cast<__nv_bfloat162*>(smem + MM_ALO + sw)     =
                __halves2bfloat162(l0, l1);
            *reinterpret_cast<__nv_bfloat162*>(smem + MM_ALO + sw + 4) =
                __halves2bfloat162(l2, l3);
        }
        // ---- stage B hi/lo: 64 n-rows x 64 k bf16 (512 uint4 -> 2/thread) ----
#pragma unroll
        for (int it = 0; it < 2; it++) {
            const int idx = tid + it * 256;        // 0..511
            const int n   = idx >> 3;
            const int seg = idx & 7;
            const uint4 vh = *reinterpret_cast<const uint4*>(
                                 g_Wt_hi + (nBase + n) * H + kc + seg * 8);
            const uint4 vl = *reinterpret_cast<const uint4*>(
                                 g_Wt_lo + (nBase + n) * H + kc + seg * 8);
            const uint32_t sw = sw128(n * 128 + seg * 16);
            *reinterpret_cast<uint4*>(smem + MM_BHI + sw) = vh;
            *reinterpret_cast<uint4*>(smem + MM_BLO + sw) = vl;
        }
        __syncthreads();

        // ---- compute: 4 k16 steps ----
#pragma unroll
        for (int kk = 0; kk < 4; kk++) {
            // A fragments (hi/lo) for 2 m-tiles.
            // quadrant order: (m-lo,k-lo) (m-hi,k-lo) (m-lo,k-hi) (m-hi,k-hi)
            uint32_t ah[2][4], al[2][4];
#pragma unroll
            for (int mt = 0; mt < 2; mt++) {
                const int arow = wm * 32 + mt * 16 + ((lmat & 1) << 3) + lrow;
                const int akb  = (kk * 16 + ((lmat >> 1) << 3)) * 2;
                const uint32_t off = sw128(arow * 128 + akb);
                ldsm_x4(ah[mt], sb + MM_AHI + off);
                ldsm_x4(al[mt], sb + MM_ALO + off);
            }
            // B fragments (hi/lo) for 4 n-tiles (x4 covers 2 n-tiles).
            // matrix order: (ntA,k-lo) (ntA,k-hi) (ntB,k-lo) (ntB,k-hi)
            uint32_t bh[4][2], bl[4][2];
#pragma unroll
            for (int np = 0; np < 2; np++) {
                const int brow = wn * 32 + np * 16 + ((lmat >> 1) << 3) + lrow;
                const int bkb  = (kk * 16 + ((lmat & 1) << 3)) * 2;
                const uint32_t off = sw128(brow * 128 + bkb);
                uint32_t th[4], tl[4];
                ldsm_x4(th, sb + MM_BHI + off);
                ldsm_x4(tl, sb + MM_BLO + off);
                bh[2 * np + 0][0] = th[0]; bh[2 * np + 0][1] = th[1];
                bh[2 * np + 1][0] = th[2]; bh[2 * np + 1][1] = th[3];
                bl[2 * np + 0][0] = tl[0]; bl[2 * np + 0][1] = tl[1];
                bl[2 * np + 1][0] = tl[2]; bl[2 * np + 1][1] = tl[3];
            }
#pragma unroll
            for (int mt = 0; mt < 2; mt++)
#pragma unroll
                for (int nt = 0; nt < 4; nt++) {
                    mma_bf16(acc[mt][nt], ah[mt], bh[nt]);
                    mma_bf16(acc[mt][nt], ah[mt], bl[nt]);
                    mma_bf16(acc[mt][nt], al[mt], bh[nt]);
                }
        }
    }

    // ---- epilogue ----
    const int gr = lane >> 2;              // 0..7
    const int gc = (lane & 3) * 2;         // 0,2,4,6
#pragma unroll
    for (int mt = 0; mt < 2; mt++) {
        const int m0 = eBase + wm * 32 + mt * 16 + gr;
        const int m1 = m0 + 8;
#pragma unroll
        for (int nt = 0; nt < 4; nt++) {
            const int n = nBase + wn * 32 + nt * 8 + gc;
            if (m0 < NENT)
                *reinterpret_cast<float2*>(g_EW1 + (size_t)m0 * H + n) =
                    make_float2(acc[mt][nt][0], acc[mt][nt][1]);
            if (m1 < NENT)
                *reinterpret_cast<float2*>(g_EW1 + (size_t)m1 * H + n) =
                    make_float2(acc[mt][nt][2], acc[mt][nt][3]);
        }
    }
}

// ===========================================================================
// Kernel 2: A = [s_emb | r_emb] @ W[256:768] + b.  (unchanged from R9)
// ===========================================================================
#define BK 32
#define SAW (BK / 2 + 1)
#define QBM 64
#define QBN 64
__global__ void __launch_bounds__(256)
aq_kernel(const int* __restrict__ s, const int* __restrict__ r,
          const float* __restrict__ ent, const float* __restrict__ rel,
          const float* __restrict__ W, const float* __restrict__ b) {
    __shared__ float4 sA[QBM * SAW];
    __shared__ float4 sW[BK * (QBN / 4)];
    __shared__ int sidx[QBM], ridx[QBM];
    const int tid   = threadIdx.x;
    const int tm    = tid >> 4;
    const int tn    = tid & 15;
    const int qBase = blockIdx.x * QBM;
    const int nBase = blockIdx.y * QBN;

    if (tid < QBM) { sidx[tid] = s[qBase + tid]; ridx[tid] = r[qBase + tid]; }
    __syncthreads();

    const int e0  = tid >> 3;
    const int k4  = tid & 7;
    const int swk = tid >> 4;
    const int swc = tid & 15;

    float2 acc[4][2];
#pragma unroll
    for (int e = 0; e < 4; e++) {
        acc[e][0] = make_float2(0.f, 0.f);
        acc[e][1] = make_float2(0.f, 0.f);
    }

    auto aSrc = [&](int kc, int e) -> const float* {
        return (kc < H) ? ent + (size_t)sidx[e] * H + kc
                        : rel + (size_t)ridx[e] * H + (kc - H);
    };

    float4 pa0 = *reinterpret_cast<const float4*>(aSrc(0, e0)      + k4 * 4);
    float4 pa1 = *reinterpret_cast<const float4*>(aSrc(0, e0 + 32) + k4 * 4);
    float4 pw0 = *(reinterpret_cast<const float4*>(
                       W + (size_t)(H + swk) * H + nBase) + swc);
    float4 pw1 = *(reinterpret_cast<const float4*>(
                       W + (size_t)(H + swk + 16) * H + nBase) + swc);

#pragma unroll 1
    for (int kc = 0; kc < 2 * H; kc += BK) {
        if (kc) __syncthreads();
        sA[e0 * SAW + k4 * 2 + 0]        = make_float4(pa0.x, pa0.x, pa0.y, pa0.y);
        sA[e0 * SAW + k4 * 2 + 1]        = make_float4(pa0.z, pa0.z, pa0.w, pa0.w);
        sA[(e0 + 32) * SAW + k4 * 2 + 0] = make_float4(pa1.x, pa1.x, pa1.y, pa1.y);
        sA[(e0 + 32) * SAW + k4 * 2 + 1] = make_float4(pa1.z, pa1.z, pa1.w, pa1.w);
        sW[swk * (QBN / 4) + swc]        = pw0;
        sW[(swk + 16) * (QBN / 4) + swc] = pw1;
        __syncthreads();

        if (kc + BK < 2 * H) {
            const int kn = kc + BK;
            pa0 = *reinterpret_cast<const float4*>(aSrc(kn, e0)      + k4 * 4);
            pa1 = *reinterpret_cast<const float4*>(aSrc(kn, e0 + 32) + k4 * 4);
            pw0 = *(reinterpret_cast<const float4*>(
                        W + (size_t)(H + kn + swk) * H + nBase) + swc);
            pw1 = *(reinterpret_cast<const float4*>(
                        W + (size_t)(H + kn + swk + 16) * H + nBase) + swc);
        }

#pragma unroll
        for (int k2 = 0; k2 < BK / 2; k2++) {
            const float4 w0 = sW[(2 * k2) * (QBN / 4) + tn];
            const float4 w1 = sW[(2 * k2 + 1) * (QBN / 4) + tn];
#pragma unroll
            for (int e = 0; e < 4; e++) {
                const float4 a = sA[(tm * 4 + e) * SAW + k2];
                acc[e][0] = ffma2(f2lo(a), f2lo(w0), acc[e][0]);
                acc[e][1] = ffma2(f2lo(a), f2hi(w0), acc[e][1]);
                acc[e][0] = ffma2(f2hi(a), f2lo(w1), acc[e][0]);
                acc[e][1] = ffma2(f2hi(a), f2hi(w1), acc[e][1]);
            }
        }
    }

    const float4 b4 = *reinterpret_cast<const float4*>(b + nBase + tn * 4);
#pragma unroll
    for (int e = 0; e < 4; e++) {
        float* row = g_A + (size_t)(qBase + tm * 4 + e) * H + nBase;
        *reinterpret_cast<float4*>(row + tn * 4) =
            make_float4(acc[e][0].x + b4.x, acc[e][0].y + b4.y,
                        acc[e][1].x + b4.z, acc[e][1].y + b4.w);
    }
}

// ---------------------------------------------------------------------------
// Kernel 3: segment start offsets from sorted seg_ids.  (unchanged)
// ---------------------------------------------------------------------------
__global__ void starts_kernel(const int* __restrict__ seg_ids) {
    const int i = blockIdx.x * blockDim.x + threadIdx.x;
    if (i >= NTOT) return;
    const int cur  = seg_ids[i];
    const int prev = (i == 0) ? -1 : seg_ids[i - 1];
    for (int sg = prev + 1; sg <= cur; sg++) g_starts[sg] = i;
    if (i == NTOT - 1)
        for (int sg = cur + 1; sg <= NSEG; sg++) g_starts[sg] = NTOT;
}

// ---------------------------------------------------------------------------
// Kernel 4 (FUSED, QUERY-PER-BLOCK).  (unchanged from round 9)
// ---------------------------------------------------------------------------
#define QCAP 512
__global__ void __launch_bounds__(256)
scoreagg_kernel(const int* __restrict__ s, const int* __restrict__ r,
                const int* __restrict__ nbr_ids,
                const float* __restrict__ ent,
                const float* __restrict__ rel,
                const float* __restrict__ v,
                float* __restrict__ out) {
    const int q    = blockIdx.x;
    const int tid  = threadIdx.x;
    const int w    = tid >> 5;
    const int lane = tid & 31;

    __shared__ int    sbnd[SEQL + 1];
    __shared__ float  wsm[QCAP];
    __shared__ int    nsm[QCAP];
    __shared__ float  sdsum[SEQL];

    if (tid <= SEQL) sbnd[tid] = g_starts[q * SEQL + tid];
    __syncthreads();
    const int qlo  = sbnd[0];
    const int qhi  = sbnd[SEQL];
    const int qcnt = qhi - qlo;

    if (qcnt > 0) {
        const float4* aq = reinterpret_cast<const float4*>(g_A + (size_t)q * H);
        const float4* vv = reinterpret_cast<const float4*>(v);
        const float4 a0 = aq[lane], a1 = aq[lane + 32];
        const float4 v0 = vv[lane], v1 = vv[lane + 32];

        for (int j0 = qlo + w; j0 < qhi; j0 += 16) {
            const int j1   = j0 + 8;
            const bool h1  = (j1 < qhi);
            const int n0   = nbr_ids[j0];
            const int n1   = nbr_ids[h1 ? j1 : j0];

            const float4* ewp0 = reinterpret_cast<const float4*>(
                                     g_EW1 + (size_t)n0 * H);
            const float4* ewp1 = reinterpret_cast<const float4*>(
                                     g_EW1 + (size_t)n1 * H);
            const float4 p0 = ewp0[lane], p1 = ewp0[lane + 32];
            const float4 r0 = ewp1[lane], r1 = ewp1[lane + 32];

            float sc0, sc1;
            sc0 = tanh_fast(p0.x + a0.x) * v0.x;
            sc1 = tanh_fast(r0.x + a0.x) * v0.x;
            sc0 = fmaf(tanh_fast(p0.y + a0.y), v0.y, sc0);
            sc1 = fmaf(tanh_fast(r0.y + a0.y), v0.y, sc1);
            sc0 = fmaf(tanh_fast(p0.z + a0.z), v0.z, sc0);
            sc1 = fmaf(tanh_fast(r0.z + a0.z), v0.z, sc1);
            sc0 = fmaf(tanh_fast(p0.w + a0.w), v0.w, sc0);
            sc1 = fmaf(tanh_fast(r0.w + a0.w), v0.w, sc1);
            sc0 = fmaf(tanh_fast(p1.x + a1.x), v1.x, sc0);
            sc1 = fmaf(tanh_fast(r1.x + a1.x), v1.x, sc1);
            sc0 = fmaf(tanh_fast(p1.y + a1.y), v1.y, sc0);
            sc1 = fmaf(tanh_fast(r1.y + a1.y), v1.y, sc1);
            sc0 = fmaf(tanh_fast(p1.z + a1.z), v1.z, sc0);
            sc1 = fmaf(tanh_fast(r1.z + a1.z), v1.z, sc1);
            sc0 = fmaf(tanh_fast(p1.w + a1.w), v1.w, sc0);
            sc1 = fmaf(tanh_fast(r1.w + a1.w), v1.w, sc1);
#pragma unroll
            for (int o = 16; o; o >>= 1) {
                sc0 += __shfl_xor_sync(0xffffffffu, sc0, o);
                sc1 += __shfl_xor_sync(0xffffffffu, sc1, o);
            }
            if (lane == 0) {
                const float e0 = __expf(sc0);
                const int k0 = j0 - qlo;
                if (k0 < QCAP) { wsm[k0] = e0; nsm[k0] = n0; }
                else           g_scores[j0] = e0;
                if (h1) {
                    const float e1 = __expf(sc1);
                    const int k1 = j1 - qlo;
                    if (k1 < QCAP) { wsm[k1] = e1; nsm[k1] = n1; }
                    else           g_scores[j1] = e1;
                }
            }
        }
    }
    __syncthreads();

    for (int t = w; t < SEQL; t += 8) {
        const int slo = sbnd[t]     - qlo;
        const int shi = sbnd[t + 1] - qlo;
        float d = 0.0f;
        for (int k = slo + lane; k < shi; k += 32)
            d += (k < QCAP) ? wsm[k] : g_scores[qlo + k];
#pragma unroll
        for (int o = 16; o; o >>= 1) d += __shfl_xor_sync(0xffffffffu, d, o);
        if (lane == 0) sdsum[t] = d;
    }

    const int g  = tid >> 7;
    const int h2 = tid & 127;
    const float2 s2 = *reinterpret_cast<const float2*>(
                          ent + (size_t)s[q] * H + 2 * h2);
    const float2 r2 = *reinterpret_cast<const float2*>(
                          rel + (size_t)r[q] * H + 2 * h2);
    __syncthreads();

    float* qout = out + (size_t)q * SEQL * (3 * H);
#pragma unroll 1
    for (int t = g; t < SEQL; t += 2) {
        float* row = qout + (size_t)t * (3 * H);
        float2* rowA = reinterpret_cast<float2*>(row);
        float2* rowS = reinterpret_cast<float2*>(row + H);
        float2* rowR = reinterpret_cast<float2*>(row + 2 * H);
        const int slo = sbnd[t]     - qlo;
        const int shi = sbnd[t + 1] - qlo;

        if (slo >= shi) {
            rowA[h2] = make_float2(0.f, 0.f);
            rowS[h2] = make_float2(0.f, 0.f);
            rowR[h2] = make_float2(0.f, 0.f);
            continue;
        }
        const float inv = 1.0f / sdsum[t];
        const int c = min(shi, QCAP);

        float2 a0 = make_float2(0.f, 0.f), a1 = make_float2(0.f, 0.f);
        float2 a2 = make_float2(0.f, 0.f), a3 = make_float2(0.f, 0.f);
        int k = slo;
        for (; k + 3 < c; k += 4) {
            const float w0 = wsm[k],     w1 = wsm[k + 1];
            const float w2 = wsm[k + 2], w3 = wsm[k + 3];
            const float2 e0 = *reinterpret_cast<const float2*>(
                                  ent + (size_t)nsm[k] * H + 2 * h2);
            const float2 e1 = *reinterpret_cast<const float2*>(
                                  ent + (size_t)nsm[k + 1] * H + 2 * h2);
            const float2 e2 = *reinterpret_cast<const float2*>(
                                  ent + (size_t)nsm[k + 2] * H + 2 * h2);
            const float2 e3 = *reinterpret_cast<const float2*>(
                                  ent + (size_t)nsm[k + 3] * H + 2 * h2);
            a0.x = fmaf(w0, e0.x, a0.x); a0.y = fmaf(w0, e0.y, a0.y);
            a1.x = fmaf(w1, e1.x, a1.x); a1.y = fmaf(w1, e1.y, a1.y);
            a2.x = fmaf(w2, e2.x, a2.x); a2.y = fmaf(w2, e2.y, a2.y);
            a3.x = fmaf(w3, e3.x, a3.x); a3.y = fmaf(w3, e3.y, a3.y);
        }
        for (; k < c; k++) {
            const float w0 = wsm[k];
            const float2 e0 = *reinterpret_cast<const float2*>(
                                  ent + (size_t)nsm[k] * H + 2 * h2);
            a0.x = fmaf(w0, e0.x, a0.x); a0.y = fmaf(w0, e0.y, a0.y);
        }
        for (; k < shi; k++) {
            const float w0 = g_scores[qlo + k];
            const float2 e0 = *reinterpret_cast<const float2*>(
                                  ent + (size_t)nbr_ids[qlo + k] * H + 2 * h2);
            a0.x = fmaf(w0, e0.x, a0.x); a0.y = fmaf(w0, e0.y, a0.y);
        }

        rowA[h2] = make_float2(((a0.x + a1.x) + (a2.x + a3.x)) * inv,
                               ((a0.y + a1.y) + (a2.y + a3.y)) * inv);
        rowS[h2] = s2;
        rowR[h2] = r2;
    }
}

// ---------------------------------------------------------------------------
extern "C" void kernel_launch(void* const* d_in, const int* in_sizes, int n_in,
                              void* d_out, int out_size) {
    const int*   s    = (const int*)d_in[0];
    const int*   r    = (const int*)d_in[1];
    const int*   nbr  = (const int*)d_in[2];
    const int*   segi = (const int*)d_in[3];
    const float* ent  = (const float*)d_in[4];
    const float* rel  = (const float*)d_in[5];
    const float* W    = (const float*)d_in[6];
    const float* b    = (const float*)d_in[7];
    const float* v    = (const float*)d_in[8];
    float* out = (float*)d_out;

    cudaFuncSetAttribute(ew1_mma_kernel,
                         cudaFuncAttributeMaxDynamicSharedMemorySize, MM_SMEM);

    starts_kernel<<<(NTOT + 255) / 256, 256>>>(segi);
    wsplit_kernel<<<64, 256>>>(W);
    ew1_mma_kernel<<<dim3((NENT + 127) / 128, 4), 256, MM_SMEM>>>(ent);
    aq_kernel<<<dim3(BQ / QBM, H / QBN), 256>>>(s, r, ent, rel, W, b);
    scoreagg_kernel<<<BQ, 256>>>(s, r, nbr, ent, rel, v, out);
}

// round 12
// speedup vs baseline: 1.9258x; 1.0586x over previous
#include <cuda_runtime.h>
#include <cuda_bf16.h>
#include <cstdint>

#define H     256
#define SEQL  10
#define BQ    2048
#define NTOT  327680
#define NSEG  (BQ * SEQL)  // 20480
#define NENT  20000

// ---------------- scratch (no cudaMalloc allowed) ----------------
__device__ float g_EW1[NENT * H];      // ent_embeds @ W1   (20.5 MB)
__device__ float g_A[BQ * H];          // s@W2 + r@W3 + b   (2 MB)
__device__ float g_scores[NTOT];       // spill store for huge queries (rare)
__device__ int   g_starts[NSEG + 1];   // segment start offsets
__device__ __nv_bfloat16 g_Wt_hi[H * H];  // W1^T hi (bf16), [n][k]
__device__ __nv_bfloat16 g_Wt_lo[H * H];  // W1^T lo residual

// Packed fp32x2 FMA (Blackwell): two fp32 FMAs per instruction.
__device__ __forceinline__ float2 ffma2(float2 a, float2 b, float2 c) {
    float2 d;
    asm("fma.rn.f32x2 %0, %1, %2, %3;"
        : "=l"(reinterpret_cast<unsigned long long&>(d))
        : "l"(reinterpret_cast<const unsigned long long&>(a)),
          "l"(reinterpret_cast<const unsigned long long&>(b)),
          "l"(reinterpret_cast<const unsigned long long&>(c)));
    return d;
}

__device__ __forceinline__ float tanh_fast(float x) {
    float y;
    asm("tanh.approx.f32 %0, %1;" : "=f"(y) : "f"(x));
    return y;
}

__device__ __forceinline__ float2 f2lo(float4 v) { return make_float2(v.x, v.y); }
__device__ __forceinline__ float2 f2hi(float4 v) { return make_float2(v.z, v.w); }

__device__ __forceinline__ uint32_t smem_u32(const void* p) {
    uint32_t a;
    asm("{ .reg .u64 t; cvta.to.shared.u64 t, %1; cvt.u32.u64 %0, t; }"
        : "=r"(a) : "l"(p));
    return a;
}

__device__ __forceinline__ uint32_t sw128(uint32_t x) {
    return x ^ ((x >> 3) & 0x70);
}

__device__ __forceinline__ void ldsm_x4(uint32_t* r, uint32_t addr) {
    asm volatile("ldmatrix.sync.aligned.m8n8.x4.shared.b16 {%0,%1,%2,%3}, [%4];"
                 : "=r"(r[0]), "=r"(r[1]), "=r"(r[2]), "=r"(r[3]) : "r"(addr));
}

__device__ __forceinline__ void mma_bf16(float* c, const uint32_t* a,
                                         const uint32_t* b) {
    asm volatile(
        "mma.sync.aligned.m16n8k16.row.col.f32.bf16.bf16.f32 "
        "{%0,%1,%2,%3}, {%4,%5,%6,%7}, {%8,%9}, {%0,%1,%2,%3};"
        : "+f"(c[0]), "+f"(c[1]), "+f"(c[2]), "+f"(c[3])
        : "r"(a[0]), "r"(a[1]), "r"(a[2]), "r"(a[3]), "r"(b[0]), "r"(b[1]));
}

// ===========================================================================
// Kernel 0 (FUSED prep): blocks [0,64) transpose+split W1; blocks [64,1344)
// compute segment start offsets from sorted seg_ids. Independent work.
// ===========================================================================
__global__ void __launch_bounds__(256)
prep_kernel(const int* __restrict__ seg_ids, const float* __restrict__ W) {
    if (blockIdx.x < 64) {
        __shared__ float t[32][33];
        const int bx = blockIdx.x & 7;       // k tile
        const int by = blockIdx.x >> 3;      // n tile
        const int tx = threadIdx.x & 31;
        const int ty = threadIdx.x >> 5;
#pragma unroll
        for (int i = 0; i < 4; i++) {
            const int k = bx * 32 + ty + i * 8;
            const int n = by * 32 + tx;
            t[ty + i * 8][tx] = W[k * H + n];
        }
        __syncthreads();
#pragma unroll
        for (int i = 0; i < 4; i++) {
            const int n = by * 32 + ty + i * 8;
            const int k = bx * 32 + tx;
            const float x = t[tx][ty + i * 8];
            const __nv_bfloat16 hi = __float2bfloat16(x);
            const __nv_bfloat16 lo = __float2bfloat16(x - __bfloat162float(hi));
            g_Wt_hi[n * H + k] = hi;
            g_Wt_lo[n * H + k] = lo;
        }
    } else {
        const int i = (blockIdx.x - 64) * 256 + threadIdx.x;
        if (i >= NTOT) return;
        const int cur  = seg_ids[i];
        const int prev = (i == 0) ? -1 : seg_ids[i - 1];
        for (int sg = prev + 1; sg <= cur; sg++) g_starts[sg] = i;
        if (i == NTOT - 1)
            for (int sg = cur + 1; sg <= NSEG; sg++) g_starts[sg] = NTOT;
    }
}

// ===========================================================================
// Kernel 1 (MERGED GEMMs, one launch, 884 blocks):
//  blocks [0, 256):    aq path  — A = [s|r] @ W[256:768] + b, 32x64 FFMA2 tiles
//  blocks [256, 884):  ew1 path — EW1 = ent @ W1 via HMMA bf16 hi/lo,
//                      128x64 tiles, K chunks of 64 (R11-verified).
// Both paths independent; mixing them in one grid fills all SMs and hides
// aq's barrier latency under ew1's tensor work.
// ===========================================================================
#define AQ_BLOCKS  256              // 64 qBase x 4 nBase
#define EW1_BLOCKS 628              // 157 eBase x 4 nBase
#define MM_AHI 0
#define MM_ALO 16384
#define MM_BHI 32768
#define MM_BLO 40960
#define MM_SMEM 49152

// ---- aq sub-kernel: QBM=32, QBN=64, BK=32, FFMA2, register prefetch ----
__device__ __forceinline__ void aq_path(char* smem, int bid,
                                        const int* __restrict__ s,
                                        const int* __restrict__ r,
                                        const float* __restrict__ ent,
                                        const float* __restrict__ rel,
                                        const float* __restrict__ W,
                                        const float* __restrict__ b) {
    float4* sA = reinterpret_cast<float4*>(smem);            // 32*17 = 544 f4
    float4* sW = reinterpret_cast<float4*>(smem + 8704);     // 512 f4
    int* sidx  = reinterpret_cast<int*>(smem + 8704 + 8192); // 32
    int* ridx  = sidx + 32;

    const int tid   = threadIdx.x;
    const int tm    = tid >> 4;            // 0..15 (2 rows each)
    const int tn    = tid & 15;            // 0..15 (4 cols)
    const int qBase = (bid & 63) * 32;
    const int nBase = (bid >> 6) * 64;

    if (tid < 32) { sidx[tid] = s[qBase + tid]; ridx[tid] = r[qBase + tid]; }
    __syncthreads();

    const int e0  = tid >> 3;              // 0..31 A row
    const int k4  = tid & 7;               // A f4-in-row
    const int swk = tid >> 4;              // W rows swk, swk+16
    const int swc = tid & 15;

    float2 acc[2][2];
#pragma unroll
    for (int e = 0; e < 2; e++) {
        acc[e][0] = make_float2(0.f, 0.f);
        acc[e][1] = make_float2(0.f, 0.f);
    }

    auto aSrc = [&](int kc, int e) -> const float* {
        return (kc < H) ? ent + (size_t)sidx[e] * H + kc
                        : rel + (size_t)ridx[e] * H + (kc - H);
    };

    float4 pa  = *reinterpret_cast<const float4*>(aSrc(0, e0) + k4 * 4);
    float4 pw0 = *(reinterpret_cast<const float4*>(
                       W + (size_t)(H + swk) * H + nBase) + swc);
    float4 pw1 = *(reinterpret_cast<const float4*>(
                       W + (size_t)(H + swk + 16) * H + nBase) + swc);

#pragma unroll 1
    for (int kc = 0; kc < 2 * H; kc += 32) {
        if (kc) __syncthreads();
        sA[e0 * 17 + k4 * 2 + 0] = make_float4(pa.x, pa.x, pa.y, pa.y);
        sA[e0 * 17 + k4 * 2 + 1] = make_float4(pa.z, pa.z, pa.w, pa.w);
        sW[swk * 16 + swc]        = pw0;
        sW[(swk + 16) * 16 + swc] = pw1;
        __syncthreads();

        if (kc + 32 < 2 * H) {
            const int kn = kc + 32;
            pa  = *reinterpret_cast<const float4*>(aSrc(kn, e0) + k4 * 4);
            pw0 = *(reinterpret_cast<const float4*>(
                        W + (size_t)(H + kn + swk) * H + nBase) + swc);
            pw1 = *(reinterpret_cast<const float4*>(
                        W + (size_t)(H + kn + swk + 16) * H + nBase) + swc);
        }

#pragma unroll
        for (int k2 = 0; k2 < 16; k2++) {
            const float4 w0 = sW[(2 * k2) * 16 + tn];
            const float4 w1 = sW[(2 * k2 + 1) * 16 + tn];
#pragma unroll
            for (int e = 0; e < 2; e++) {
                const float4 a = sA[(tm * 2 + e) * 17 + k2];
                acc[e][0] = ffma2(f2lo(a), f2lo(w0), acc[e][0]);
                acc[e][1] = ffma2(f2lo(a), f2hi(w0), acc[e][1]);
                acc[e][0] = ffma2(f2hi(a), f2lo(w1), acc[e][0]);
                acc[e][1] = ffma2(f2hi(a), f2hi(w1), acc[e][1]);
            }
        }
    }

    const float4 b4 = *reinterpret_cast<const float4*>(b + nBase + tn * 4);
#pragma unroll
    for (int e = 0; e < 2; e++) {
        float* row = g_A + (size_t)(qBase + tm * 2 + e) * H + nBase;
        *reinterpret_cast<float4*>(row + tn * 4) =
            make_float4(acc[e][0].x + b4.x, acc[e][0].y + b4.y,
                        acc[e][1].x + b4.z, acc[e][1].y + b4.w);
    }
}

// ---- ew1 sub-kernel: HMMA bf16 hi/lo (verified in R11) ----
__device__ __forceinline__ void ew1_path(char* smem, int bid,
                                         const float* __restrict__ ent) {
    const uint32_t sb = smem_u32(smem);
    const int tid   = threadIdx.x;
    const int wid   = tid >> 5;
    const int lane  = tid & 31;
    const int wm    = wid & 3;
    const int wn    = wid >> 2;
    const int eBase = (bid % 157) * 128;
    const int nBase = (bid / 157) * 64;

    const int lmat = lane >> 3;
    const int lrow = lane & 7;

    float acc[2][4][4];
#pragma unroll
    for (int mt = 0; mt < 2; mt++)
#pragma unroll
        for (int nt = 0; nt < 4; nt++)
#pragma unroll
            for (int j = 0; j < 4; j++) acc[mt][nt][j] = 0.0f;

#pragma unroll 1
    for (int c = 0; c < 4; c++) {
        const int kc = c * 64;
        if (c) __syncthreads();

#pragma unroll
        for (int it = 0; it < 8; it++) {
            const int idx = tid + it * 256;
            const int row = idx >> 4;
            const int q4  = idx & 15;
            int er = eBase + row; if (er >= NENT) er = 0;
            const float4 x = *reinterpret_cast<const float4*>(
                                 ent + (size_t)er * H + kc + q4 * 4);
            const __nv_bfloat16 h0 = __float2bfloat16(x.x);
            const __nv_bfloat16 h1 = __float2bfloat16(x.y);
            const __nv_bfloat16 h2 = __float2bfloat16(x.z);
            const __nv_bfloat16 h3 = __float2bfloat16(x.w);
            const __nv_bfloat16 l0 = __float2bfloat16(x.x - __bfloat162float(h0));
            const __nv_bfloat16 l1 = __float2bfloat16(x.y - __bfloat162float(h1));
            const __nv_bfloat16 l2 = __float2bfloat16(x.z - __bfloat162float(h2));
            const __nv_bfloat16 l3 = __float2bfloat16(x.w - __bfloat162float(h3));
            const uint32_t sw = sw128(row * 128 + q4 * 8);
            *reinterpret_cast<__nv_bfloat162*>(smem + MM_AHI + sw)     =
                __halves2bfloat162(h0, h1);
            *reinterpret_cast<__nv_bfloat162*>(smem + MM_AHI + sw + 4) =
                __halves2bfloat162(h2, h3);
            *reinterpret_cast<__nv_bfloat162*>(smem + MM_ALO + sw)     =
                __halves2bfloat162(l0, l1);
            *reinterpret_cast<__nv_bfloat162*>(smem + MM_ALO + sw + 4) =
                __halves2bfloat162(l2, l3);
        }
#pragma unroll
        for (int it = 0; it < 2; it++) {
            const int idx = tid + it * 256;
            const int n   = idx >> 3;
            const int seg = idx & 7;
            const uint4 vh = *reinterpret_cast<const uint4*>(
                                 g_Wt_hi + (nBase + n) * H + kc + seg * 8);
            const uint4 vl = *reinterpret_cast<const uint4*>(
                                 g_Wt_lo + (nBase + n) * H + kc + seg * 8);
            const uint32_t sw = sw128(n * 128 + seg * 16);
            *reinterpret_cast<uint4*>(smem + MM_BHI + sw) = vh;
            *reinterpret_cast<uint4*>(smem + MM_BLO + sw) = vl;
        }
        __syncthreads();

#pragma unroll
        for (int kk = 0; kk < 4; kk++) {
            uint32_t ah[2][4], al[2][4];
#pragma unroll
            for (int mt = 0; mt < 2; mt++) {
                const int arow = wm * 32 + mt * 16 + ((lmat & 1) << 3) + lrow;
                const int akb  = (kk * 16 + ((lmat >> 1) << 3)) * 2;
                const uint32_t off = sw128(arow * 128 + akb);
                ldsm_x4(ah[mt], sb + MM_AHI + off);
                ldsm_x4(al[mt], sb + MM_ALO + off);
            }
            uint32_t bh[4][2], bl[4][2];
#pragma unroll
            for (int np = 0; np < 2; np++) {
                const int brow = wn * 32 + np * 16 + ((lmat >> 1) << 3) + lrow;
                const int bkb  = (kk * 16 + ((lmat & 1) << 3)) * 2;
                const uint32_t off = sw128(brow * 128 + bkb);
                uint32_t th[4], tl[4];
                ldsm_x4(th, sb + MM_BHI + off);
                ldsm_x4(tl, sb + MM_BLO + off);
                bh[2 * np + 0][0] = th[0]; bh[2 * np + 0][1] = th[1];
                bh[2 * np + 1][0] = th[2]; bh[2 * np + 1][1] = th[3];
                bl[2 * np + 0][0] = tl[0]; bl[2 * np + 0][1] = tl[1];
                bl[2 * np + 1][0] = tl[2]; bl[2 * np + 1][1] = tl[3];
            }
#pragma unroll
            for (int mt = 0; mt < 2; mt++)
#pragma unroll
                for (int nt = 0; nt < 4; nt++) {
                    mma_bf16(acc[mt][nt], ah[mt], bh[nt]);
                    mma_bf16(acc[mt][nt], ah[mt], bl[nt]);
                    mma_bf16(acc[mt][nt], al[mt], bh[nt]);
                }
        }
    }

    const int gr = lane >> 2;
    const int gc = (lane & 3) * 2;
#pragma unroll
    for (int mt = 0; mt < 2; mt++) {
        const int m0 = eBase + wm * 32 + mt * 16 + gr;
        const int m1 = m0 + 8;
#pragma unroll
        for (int nt = 0; nt < 4; nt++) {
            const int n = nBase + wn * 32 + nt * 8 + gc;
            if (m0 < NENT)
                *reinterpret_cast<float2*>(g_EW1 + (size_t)m0 * H + n) =
                    make_float2(acc[mt][nt][0], acc[mt][nt][1]);
            if (m1 < NENT)
                *reinterpret_cast<float2*>(g_EW1 + (size_t)m1 * H + n) =
                    make_float2(acc[mt][nt][2], acc[mt][nt][3]);
        }
    }
}

__global__ void __launch_bounds__(256)
gemm_kernel(const float* __restrict__ ent,
            const int* __restrict__ s, const int* __restrict__ r,
            const float* __restrict__ rel,
            const float* __restrict__ W, const float* __restrict__ b) {
    extern __shared__ char smem[];
    const int bid = blockIdx.x;
    if (bid < AQ_BLOCKS) aq_path(smem, bid, s, r, ent, rel, W, b);
    else                 ew1_path(smem, bid - AQ_BLOCKS, ent);
}

// ---------------------------------------------------------------------------
// Kernel 2 (FUSED, QUERY-PER-BLOCK).  (unchanged from round 9/11)
// ---------------------------------------------------------------------------
#define QCAP 512
__global__ void __launch_bounds__(256)
scoreagg_kernel(const int* __restrict__ s, const int* __restrict__ r,
                const int* __restrict__ nbr_ids,
                const float* __restrict__ ent,
                const float* __restrict__ rel,
                const float* __restrict__ v,
                float* __restrict__ out) {
    const int q    = blockIdx.x;
    const int tid  = threadIdx.x;
    const int w    = tid >> 5;
    const int lane = tid & 31;

    __shared__ int    sbnd[SEQL + 1];
    __shared__ float  wsm[QCAP];
    __shared__ int    nsm[QCAP];
    __shared__ float  sdsum[SEQL];

    if (tid <= SEQL) sbnd[tid] = g_starts[q * SEQL + tid];
    __syncthreads();
    const int qlo  = sbnd[0];
    const int qhi  = sbnd[SEQL];
    const int qcnt = qhi - qlo;

    if (qcnt > 0) {
        const float4* aq = reinterpret_cast<const float4*>(g_A + (size_t)q * H);
        const float4* vv = reinterpret_cast<const float4*>(v);
        const float4 a0 = aq[lane], a1 = aq[lane + 32];
        const float4 v0 = vv[lane], v1 = vv[lane + 32];

        for (int j0 = qlo + w; j0 < qhi; j0 += 16) {
            const int j1   = j0 + 8;
            const bool h1  = (j1 < qhi);
            const int n0   = nbr_ids[j0];
            const int n1   = nbr_ids[h1 ? j1 : j0];

            const float4* ewp0 = reinterpret_cast<const float4*>(
                                     g_EW1 + (size_t)n0 * H);
            const float4* ewp1 = reinterpret_cast<const float4*>(
                                     g_EW1 + (size_t)n1 * H);
            const float4 p0 = ewp0[lane], p1 = ewp0[lane + 32];
            const float4 r0 = ewp1[lane], r1 = ewp1[lane + 32];

            float sc0, sc1;
            sc0 = tanh_fast(p0.x + a0.x) * v0.x;
            sc1 = tanh_fast(r0.x + a0.x) * v0.x;
            sc0 = fmaf(tanh_fast(p0.y + a0.y), v0.y, sc0);
            sc1 = fmaf(tanh_fast(r0.y + a0.y), v0.y, sc1);
            sc0 = fmaf(tanh_fast(p0.z + a0.z), v0.z, sc0);
            sc1 = fmaf(tanh_fast(r0.z + a0.z), v0.z, sc1);
            sc0 = fmaf(tanh_fast(p0.w + a0.w), v0.w, sc0);
            sc1 = fmaf(tanh_fast(r0.w + a0.w), v0.w, sc1);
            sc0 = fmaf(tanh_fast(p1.x + a1.x), v1.x, sc0);
            sc1 = fmaf(tanh_fast(r1.x + a1.x), v1.x, sc1);
            sc0 = fmaf(tanh_fast(p1.y + a1.y), v1.y, sc0);
            sc1 = fmaf(tanh_fast(r1.y + a1.y), v1.y, sc1);
            sc0 = fmaf(tanh_fast(p1.z + a1.z), v1.z, sc0);
            sc1 = fmaf(tanh_fast(r1.z + a1.z), v1.z, sc1);
            sc0 = fmaf(tanh_fast(p1.w + a1.w), v1.w, sc0);
            sc1 = fmaf(tanh_fast(r1.w + a1.w), v1.w, sc1);
#pragma unroll
            for (int o = 16; o; o >>= 1) {
                sc0 += __shfl_xor_sync(0xffffffffu, sc0, o);
                sc1 += __shfl_xor_sync(0xffffffffu, sc1, o);
            }
            if (lane == 0) {
                const float e0 = __expf(sc0);
                const int k0 = j0 - qlo;
                if (k0 < QCAP) { wsm[k0] = e0; nsm[k0] = n0; }
                else           g_scores[j0] = e0;
                if (h1) {
                    const float e1 = __expf(sc1);
                    const int k1 = j1 - qlo;
                    if (k1 < QCAP) { wsm[k1] = e1; nsm[k1] = n1; }
                    else           g_scores[j1] = e1;
                }
            }
        }
    }
    __syncthreads();

    for (int t = w; t < SEQL; t += 8) {
        const int slo = sbnd[t]     - qlo;
        const int shi = sbnd[t + 1] - qlo;
        float d = 0.0f;
        for (int k = slo + lane; k < shi; k += 32)
            d += (k < QCAP) ? wsm[k] : g_scores[qlo + k];
#pragma unroll
        for (int o = 16; o; o >>= 1) d += __shfl_xor_sync(0xffffffffu, d, o);
        if (lane == 0) sdsum[t] = d;
    }

    const int g  = tid >> 7;
    const int h2 = tid & 127;
    const float2 s2 = *reinterpret_cast<const float2*>(
                          ent + (size_t)s[q] * H + 2 * h2);
    const float2 r2 = *reinterpret_cast<const float2*>(
                          rel + (size_t)r[q] * H + 2 * h2);
    __syncthreads();

    float* qout = out + (size_t)q * SEQL * (3 * H);
#pragma unroll 1
    for (int t = g; t < SEQL; t += 2) {
        float* row = qout + (size_t)t * (3 * H);
        float2* rowA = reinterpret_cast<float2*>(row);
        float2* rowS = reinterpret_cast<float2*>(row + H);
        float2* rowR = reinterpret_cast<float2*>(row + 2 * H);
        const int slo = sbnd[t]     - qlo;
        const int shi = sbnd[t + 1] - qlo;

        if (slo >= shi) {
            rowA[h2] = make_float2(0.f, 0.f);
            rowS[h2] = make_float2(0.f, 0.f);
            rowR[h2] = make_float2(0.f, 0.f);
            continue;
        }
        const float inv = 1.0f / sdsum[t];
        const int c = min(shi, QCAP);

        float2 a0 = make_float2(0.f, 0.f), a1 = make_float2(0.f, 0.f);
        float2 a2 = make_float2(0.f, 0.f), a3 = make_float2(0.f, 0.f);
        int k = slo;
        for (; k + 3 < c; k += 4) {
            const float w0 = wsm[k],     w1 = wsm[k + 1];
            const float w2 = wsm[k + 2], w3 = wsm[k + 3];
            const float2 e0 = *reinterpret_cast<const float2*>(
                                  ent + (size_t)nsm[k] * H + 2 * h2);
            const float2 e1 = *reinterpret_cast<const float2*>(
                                  ent + (size_t)nsm[k + 1] * H + 2 * h2);
            const float2 e2 = *reinterpret_cast<const float2*>(
                                  ent + (size_t)nsm[k + 2] * H + 2 * h2);
            const float2 e3 = *reinterpret_cast<const float2*>(
                                  ent + (size_t)nsm[k + 3] * H + 2 * h2);
            a0.x = fmaf(w0, e0.x, a0.x); a0.y = fmaf(w0, e0.y, a0.y);
            a1.x = fmaf(w1, e1.x, a1.x); a1.y = fmaf(w1, e1.y, a1.y);
            a2.x = fmaf(w2, e2.x, a2.x); a2.y = fmaf(w2, e2.y, a2.y);
            a3.x = fmaf(w3, e3.x, a3.x); a3.y = fmaf(w3, e3.y, a3.y);
        }
        for (; k < c; k++) {
            const float w0 = wsm[k];
            const float2 e0 = *reinterpret_cast<const float2*>(
                                  ent + (size_t)nsm[k] * H + 2 * h2);
            a0.x = fmaf(w0, e0.x, a0.x); a0.y = fmaf(w0, e0.y, a0.y);
        }
        for (; k < shi; k++) {
            const float w0 = g_scores[qlo + k];
            const float2 e0 = *reinterpret_cast<const float2*>(
                                  ent + (size_t)nbr_ids[qlo + k] * H + 2 * h2);
            a0.x = fmaf(w0, e0.x, a0.x); a0.y = fmaf(w0, e0.y, a0.y);
        }

        rowA[h2] = make_float2(((a0.x + a1.x) + (a2.x + a3.x)) * inv,
                               ((a0.y + a1.y) + (a2.y + a3.y)) * inv);
        rowS[h2] = s2;
        rowR[h2] = r2;
    }
}

// ---------------------------------------------------------------------------
extern "C" void kernel_launch(void* const* d_in, const int* in_sizes, int n_in,
                              void* d_out, int out_size) {
    const int*   s    = (const int*)d_in[0];
    const int*   r    = (const int*)d_in[1];
    const int*   nbr  = (const int*)d_in[2];
    const int*   segi = (const int*)d_in[3];
    const float* ent  = (const float*)d_in[4];
    const float* rel  = (const float*)d_in[5];
    const float* W    = (const float*)d_in[6];
    const float* b    = (const float*)d_in[7];
    const float* v    = (const float*)d_in[8];
    float* out = (float*)d_out;

    cudaFuncSetAttribute(gemm_kernel,
                         cudaFuncAttributeMaxDynamicSharedMemorySize, MM_SMEM);

    prep_kernel<<<64 + (NTOT + 255) / 256, 256>>>(segi, W);
    gemm_kernel<<<AQ_BLOCKS + EW1_BLOCKS, 256, MM_SMEM>>>(ent, s, r, rel, W, b);
    scoreagg_kernel<<<BQ, 256>>>(s, r, nbr, ent, rel, v, out);
}

// round 13
// speedup vs baseline: 2.0142x; 1.0459x over previous
#include <cuda_runtime.h>
#include <cuda_bf16.h>
#include <cuda_fp16.h>
#include <cstdint>

#define H     256
#define SEQL  10
#define BQ    2048
#define NTOT  327680
#define NSEG  (BQ * SEQL)  // 20480
#define NENT  20000

// ---------------- scratch (no cudaMalloc allowed) ----------------
__device__ __half g_EW1h[NENT * H];    // ent_embeds @ W1 in fp16 (10 MB)
__device__ float g_A[BQ * H];          // s@W2 + r@W3 + b   (2 MB)
__device__ float g_scores[NTOT];       // spill store for huge queries (rare)
__device__ int   g_starts[NSEG + 1];   // segment start offsets
__device__ __nv_bfloat16 g_Wt_hi[H * H];  // W1^T hi (bf16), [n][k]
__device__ __nv_bfloat16 g_Wt_lo[H * H];  // W1^T lo residual

// Packed fp32x2 FMA (Blackwell): two fp32 FMAs per instruction.
__device__ __forceinline__ float2 ffma2(float2 a, float2 b, float2 c) {
    float2 d;
    asm("fma.rn.f32x2 %0, %1, %2, %3;"
        : "=l"(reinterpret_cast<unsigned long long&>(d))
        : "l"(reinterpret_cast<const unsigned long long&>(a)),
          "l"(reinterpret_cast<const unsigned long long&>(b)),
          "l"(reinterpret_cast<const unsigned long long&>(c)));
    return d;
}

__device__ __forceinline__ float tanh_fast(float x) {
    float y;
    asm("tanh.approx.f32 %0, %1;" : "=f"(y) : "f"(x));
    return y;
}

__device__ __forceinline__ float2 f2lo(float4 v) { return make_float2(v.x, v.y); }
__device__ __forceinline__ float2 f2hi(float4 v) { return make_float2(v.z, v.w); }

__device__ __forceinline__ uint32_t smem_u32(const void* p) {
    uint32_t a;
    asm("{ .reg .u64 t; cvta.to.shared.u64 t, %1; cvt.u32.u64 %0, t; }"
        : "=r"(a) : "l"(p));
    return a;
}

__device__ __forceinline__ uint32_t sw128(uint32_t x) {
    return x ^ ((x >> 3) & 0x70);
}

__device__ __forceinline__ void ldsm_x4(uint32_t* r, uint32_t addr) {
    asm volatile("ldmatrix.sync.aligned.m8n8.x4.shared.b16 {%0,%1,%2,%3}, [%4];"
                 : "=r"(r[0]), "=r"(r[1]), "=r"(r[2]), "=r"(r[3]) : "r"(addr));
}

__device__ __forceinline__ void mma_bf16(float* c, const uint32_t* a,
                                         const uint32_t* b) {
    asm volatile(
        "mma.sync.aligned.m16n8k16.row.col.f32.bf16.bf16.f32 "
        "{%0,%1,%2,%3}, {%4,%5,%6,%7}, {%8,%9}, {%0,%1,%2,%3};"
        : "+f"(c[0]), "+f"(c[1]), "+f"(c[2]), "+f"(c[3])
        : "r"(a[0]), "r"(a[1]), "r"(a[2]), "r"(a[3]), "r"(b[0]), "r"(b[1]));
}

// ===========================================================================
// Kernel 0 (FUSED prep): blocks [0,64) transpose+split W1; blocks [64,1344)
// compute segment start offsets from sorted seg_ids. Independent work.
// ===========================================================================
__global__ void __launch_bounds__(256)
prep_kernel(const int* __restrict__ seg_ids, const float* __restrict__ W) {
    if (blockIdx.x < 64) {
        __shared__ float t[32][33];
        const int bx = blockIdx.x & 7;       // k tile
        const int by = blockIdx.x >> 3;      // n tile
        const int tx = threadIdx.x & 31;
        const int ty = threadIdx.x >> 5;
#pragma unroll
        for (int i = 0; i < 4; i++) {
            const int k = bx * 32 + ty + i * 8;
            const int n = by * 32 + tx;
            t[ty + i * 8][tx] = W[k * H + n];
        }
        __syncthreads();
#pragma unroll
        for (int i = 0; i < 4; i++) {
            const int n = by * 32 + ty + i * 8;
            const int k = bx * 32 + tx;
            const float x = t[tx][ty + i * 8];
            const __nv_bfloat16 hi = __float2bfloat16(x);
            const __nv_bfloat16 lo = __float2bfloat16(x - __bfloat162float(hi));
            g_Wt_hi[n * H + k] = hi;
            g_Wt_lo[n * H + k] = lo;
        }
    } else {
        const int i = (blockIdx.x - 64) * 256 + threadIdx.x;
        if (i >= NTOT) return;
        const int cur  = seg_ids[i];
        const int prev = (i == 0) ? -1 : seg_ids[i - 1];
        for (int sg = prev + 1; sg <= cur; sg++) g_starts[sg] = i;
        if (i == NTOT - 1)
            for (int sg = cur + 1; sg <= NSEG; sg++) g_starts[sg] = NTOT;
    }
}

// ===========================================================================
// Kernel 1 (MERGED GEMMs, one launch, 884 blocks):
//  blocks [0, 256):    aq path  — A = [s|r] @ W[256:768] + b, 32x64 FFMA2 tiles
//  blocks [256, 884):  ew1 path — EW1 = ent @ W1 via HMMA bf16 hi/lo,
//                      128x64 tiles, K chunks of 64; epilogue stores fp16.
// ===========================================================================
#define AQ_BLOCKS  256              // 64 qBase x 4 nBase
#define EW1_BLOCKS 628              // 157 eBase x 4 nBase
#define MM_AHI 0
#define MM_ALO 16384
#define MM_BHI 32768
#define MM_BLO 40960
#define MM_SMEM 49152

// ---- aq sub-kernel: QBM=32, QBN=64, BK=32, FFMA2, register prefetch ----
__device__ __forceinline__ void aq_path(char* smem, int bid,
                                        const int* __restrict__ s,
                                        const int* __restrict__ r,
                                        const float* __restrict__ ent,
                                        const float* __restrict__ rel,
                                        const float* __restrict__ W,
                                        const float* __restrict__ b) {
    float4* sA = reinterpret_cast<float4*>(smem);            // 32*17 = 544 f4
    float4* sW = reinterpret_cast<float4*>(smem + 8704);     // 512 f4
    int* sidx  = reinterpret_cast<int*>(smem + 8704 + 8192); // 32
    int* ridx  = sidx + 32;

    const int tid   = threadIdx.x;
    const int tm    = tid >> 4;            // 0..15 (2 rows each)
    const int tn    = tid & 15;            // 0..15 (4 cols)
    const int qBase = (bid & 63) * 32;
    const int nBase = (bid >> 6) * 64;

    if (tid < 32) { sidx[tid] = s[qBase + tid]; ridx[tid] = r[qBase + tid]; }
    __syncthreads();

    const int e0  = tid >> 3;              // 0..31 A row
    const int k4  = tid & 7;               // A f4-in-row
    const int swk = tid >> 4;              // W rows swk, swk+16
    const int swc = tid & 15;

    float2 acc[2][2];
#pragma unroll
    for (int e = 0; e < 2; e++) {
        acc[e][0] = make_float2(0.f, 0.f);
        acc[e][1] = make_float2(0.f, 0.f);
    }

    auto aSrc = [&](int kc, int e) -> const float* {
        return (kc < H) ? ent + (size_t)sidx[e] * H + kc
                        : rel + (size_t)ridx[e] * H + (kc - H);
    };

    float4 pa  = *reinterpret_cast<const float4*>(aSrc(0, e0) + k4 * 4);
    float4 pw0 = *(reinterpret_cast<const float4*>(
                       W + (size_t)(H + swk) * H + nBase) + swc);
    float4 pw1 = *(reinterpret_cast<const float4*>(
                       W + (size_t)(H + swk + 16) * H + nBase) + swc);

#pragma unroll 1
    for (int kc = 0; kc < 2 * H; kc += 32) {
        if (kc) __syncthreads();
        sA[e0 * 17 + k4 * 2 + 0] = make_float4(pa.x, pa.x, pa.y, pa.y);
        sA[e0 * 17 + k4 * 2 + 1] = make_float4(pa.z, pa.z, pa.w, pa.w);
        sW[swk * 16 + swc]        = pw0;
        sW[(swk + 16) * 16 + swc] = pw1;
        __syncthreads();

        if (kc + 32 < 2 * H) {
            const int kn = kc + 32;
            pa  = *reinterpret_cast<const float4*>(aSrc(kn, e0) + k4 * 4);
            pw0 = *(reinterpret_cast<const float4*>(
                        W + (size_t)(H + kn + swk) * H + nBase) + swc);
            pw1 = *(reinterpret_cast<const float4*>(
                        W + (size_t)(H + kn + swk + 16) * H + nBase) + swc);
        }

#pragma unroll
        for (int k2 = 0; k2 < 16; k2++) {
            const float4 w0 = sW[(2 * k2) * 16 + tn];
            const float4 w1 = sW[(2 * k2 + 1) * 16 + tn];
#pragma unroll
            for (int e = 0; e < 2; e++) {
                const float4 a = sA[(tm * 2 + e) * 17 + k2];
                acc[e][0] = ffma2(f2lo(a), f2lo(w0), acc[e][0]);
                acc[e][1] = ffma2(f2lo(a), f2hi(w0), acc[e][1]);
                acc[e][0] = ffma2(f2hi(a), f2lo(w1), acc[e][0]);
                acc[e][1] = ffma2(f2hi(a), f2hi(w1), acc[e][1]);
            }
        }
    }

    const float4 b4 = *reinterpret_cast<const float4*>(b + nBase + tn * 4);
#pragma unroll
    for (int e = 0; e < 2; e++) {
        float* row = g_A + (size_t)(qBase + tm * 2 + e) * H + nBase;
        *reinterpret_cast<float4*>(row + tn * 4) =
            make_float4(acc[e][0].x + b4.x, acc[e][0].y + b4.y,
                        acc[e][1].x + b4.z, acc[e][1].y + b4.w);
    }
}

// ---- ew1 sub-kernel: HMMA bf16 hi/lo, fp16 output ----
__device__ __forceinline__ void ew1_path(char* smem, int bid,
                                         const float* __restrict__ ent) {
    const uint32_t sb = smem_u32(smem);
    const int tid   = threadIdx.x;
    const int wid   = tid >> 5;
    const int lane  = tid & 31;
    const int wm    = wid & 3;
    const int wn    = wid >> 2;
    const int eBase = (bid % 157) * 128;
    const int nBase = (bid / 157) * 64;

    const int lmat = lane >> 3;
    const int lrow = lane & 7;

    float acc[2][4][4];
#pragma unroll
    for (int mt = 0; mt < 2; mt++)
#pragma unroll
        for (int nt = 0; nt < 4; nt++)
#pragma unroll
            for (int j = 0; j < 4; j++) acc[mt][nt][j] = 0.0f;

#pragma unroll 1
    for (int c = 0; c < 4; c++) {
        const int kc = c * 64;
        if (c) __syncthreads();

#pragma unroll
        for (int it = 0; it < 8; it++) {
            const int idx = tid + it * 256;
            const int row = idx >> 4;
            const int q4  = idx & 15;
            int er = eBase + row; if (er >= NENT) er = 0;
            const float4 x = *reinterpret_cast<const float4*>(
                                 ent + (size_t)er * H + kc + q4 * 4);
            const __nv_bfloat16 h0 = __float2bfloat16(x.x);
            const __nv_bfloat16 h1 = __float2bfloat16(x.y);
            const __nv_bfloat16 h2 = __float2bfloat16(x.z);
            const __nv_bfloat16 h3 = __float2bfloat16(x.w);
            const __nv_bfloat16 l0 = __float2bfloat16(x.x - __bfloat162float(h0));
            const __nv_bfloat16 l1 = __float2bfloat16(x.y - __bfloat162float(h1));
            const __nv_bfloat16 l2 = __float2bfloat16(x.z - __bfloat162float(h2));
            const __nv_bfloat16 l3 = __float2bfloat16(x.w - __bfloat162float(h3));
            const uint32_t sw = sw128(row * 128 + q4 * 8);
            *reinterpret_cast<__nv_bfloat162*>(smem + MM_AHI + sw)     =
                __halves2bfloat162(h0, h1);
            *reinterpret_cast<__nv_bfloat162*>(smem + MM_AHI + sw + 4) =
                __halves2bfloat162(h2, h3);
            *reinterpret_cast<__nv_bfloat162*>(smem + MM_ALO + sw)     =
                __halves2bfloat162(l0, l1);
            *reinterpret_cast<__nv_bfloat162*>(smem + MM_ALO + sw + 4) =
                __halves2bfloat162(l2, l3);
        }
#pragma unroll
        for (int it = 0; it < 2; it++) {
            const int idx = tid + it * 256;
            const int n   = idx >> 3;
            const int seg = idx & 7;
            const uint4 vh = *reinterpret_cast<const uint4*>(
                                 g_Wt_hi + (nBase + n) * H + kc + seg * 8);
            const uint4 vl = *reinterpret_cast<const uint4*>(
                                 g_Wt_lo + (nBase + n) * H + kc + seg * 8);
            const uint32_t sw = sw128(n * 128 + seg * 16);
            *reinterpret_cast<uint4*>(smem + MM_BHI + sw) = vh;
            *reinterpret_cast<uint4*>(smem + MM_BLO + sw) = vl;
        }
        __syncthreads();

#pragma unroll
        for (int kk = 0; kk < 4; kk++) {
            uint32_t ah[2][4], al[2][4];
#pragma unroll
            for (int mt = 0; mt < 2; mt++) {
                const int arow = wm * 32 + mt * 16 + ((lmat & 1) << 3) + lrow;
                const int akb  = (kk * 16 + ((lmat >> 1) << 3)) * 2;
                const uint32_t off = sw128(arow * 128 + akb);
                ldsm_x4(ah[mt], sb + MM_AHI + off);
                ldsm_x4(al[mt], sb + MM_ALO + off);
            }
            uint32_t bh[4][2], bl[4][2];
#pragma unroll
            for (int np = 0; np < 2; np++) {
                const int brow = wn * 32 + np * 16 + ((lmat >> 1) << 3) + lrow;
                const int bkb  = (kk * 16 + ((lmat & 1) << 3)) * 2;
                const uint32_t off = sw128(brow * 128 + bkb);
                uint32_t th[4], tl[4];
                ldsm_x4(th, sb + MM_BHI + off);
                ldsm_x4(tl, sb + MM_BLO + off);
                bh[2 * np + 0][0] = th[0]; bh[2 * np + 0][1] = th[1];
                bh[2 * np + 1][0] = th[2]; bh[2 * np + 1][1] = th[3];
                bl[2 * np + 0][0] = tl[0]; bl[2 * np + 0][1] = tl[1];
                bl[2 * np + 1][0] = tl[2]; bl[2 * np + 1][1] = tl[3];
            }
#pragma unroll
            for (int mt = 0; mt < 2; mt++)
#pragma unroll
                for (int nt = 0; nt < 4; nt++) {
                    mma_bf16(acc[mt][nt], ah[mt], bh[nt]);
                    mma_bf16(acc[mt][nt], ah[mt], bl[nt]);
                    mma_bf16(acc[mt][nt], al[mt], bh[nt]);
                }
        }
    }

    // epilogue: fp32 acc -> fp16 EW1
    const int gr = lane >> 2;
    const int gc = (lane & 3) * 2;
#pragma unroll
    for (int mt = 0; mt < 2; mt++) {
        const int m0 = eBase + wm * 32 + mt * 16 + gr;
        const int m1 = m0 + 8;
#pragma unroll
        for (int nt = 0; nt < 4; nt++) {
            const int n = nBase + wn * 32 + nt * 8 + gc;
            if (m0 < NENT)
                *reinterpret_cast<__half2*>(g_EW1h + (size_t)m0 * H + n) =
                    __floats2half2_rn(acc[mt][nt][0], acc[mt][nt][1]);
            if (m1 < NENT)
                *reinterpret_cast<__half2*>(g_EW1h + (size_t)m1 * H + n) =
                    __floats2half2_rn(acc[mt][nt][2], acc[mt][nt][3]);
        }
    }
}

__global__ void __launch_bounds__(256)
gemm_kernel(const float* __restrict__ ent,
            const int* __restrict__ s, const int* __restrict__ r,
            const float* __restrict__ rel,
            const float* __restrict__ W, const float* __restrict__ b) {
    extern __shared__ char smem[];
    const int bid = blockIdx.x;
    if (bid < AQ_BLOCKS) aq_path(smem, bid, s, r, ent, rel, W, b);
    else                 ew1_path(smem, bid - AQ_BLOCKS, ent);
}

// ---------------------------------------------------------------------------
// Kernel 2 (FUSED, QUERY-PER-BLOCK): pass 1 reads fp16 EW1 (one LDG.128/lane
// per row); pass 2 gathers at float4 grain, 4 groups x 64 threads, segments
// striped by group.
// ---------------------------------------------------------------------------
#define QCAP 512
__global__ void __launch_bounds__(256)
scoreagg_kernel(const int* __restrict__ s, const int* __restrict__ r,
                const int* __restrict__ nbr_ids,
                const float* __restrict__ ent,
                const float* __restrict__ rel,
                const float* __restrict__ v,
                float* __restrict__ out) {
    const int q    = blockIdx.x;
    const int tid  = threadIdx.x;
    const int w    = tid >> 5;
    const int lane = tid & 31;

    __shared__ int    sbnd[SEQL + 1];
    __shared__ float  wsm[QCAP];
    __shared__ int    nsm[QCAP];
    __shared__ float  sdsum[SEQL];

    if (tid <= SEQL) sbnd[tid] = g_starts[q * SEQL + tid];
    __syncthreads();
    const int qlo  = sbnd[0];
    const int qhi  = sbnd[SEQL];
    const int qcnt = qhi - qlo;

    // ---- pass 1: scores (2 neighbors per warp-iteration) ----
    if (qcnt > 0) {
        // lane owns h = lane*8 .. lane*8+7
        const float4* aq = reinterpret_cast<const float4*>(g_A + (size_t)q * H);
        const float4* vv = reinterpret_cast<const float4*>(v);
        const float4 a0 = aq[2 * lane], a1 = aq[2 * lane + 1];
        const float4 v0 = vv[2 * lane], v1 = vv[2 * lane + 1];

        for (int j0 = qlo + w; j0 < qhi; j0 += 16) {
            const int j1   = j0 + 8;
            const bool h1  = (j1 < qhi);
            const int n0   = nbr_ids[j0];
            const int n1   = nbr_ids[h1 ? j1 : j0];

            const uint4 eu0 = *reinterpret_cast<const uint4*>(
                                  g_EW1h + (size_t)n0 * H + lane * 8);
            const uint4 eu1 = *reinterpret_cast<const uint4*>(
                                  g_EW1h + (size_t)n1 * H + lane * 8);
            const __half2* e0 = reinterpret_cast<const __half2*>(&eu0);
            const __half2* e1 = reinterpret_cast<const __half2*>(&eu1);
            const float2 p0 = __half22float2(e0[0]);
            const float2 p1 = __half22float2(e0[1]);
            const float2 p2 = __half22float2(e0[2]);
            const float2 p3 = __half22float2(e0[3]);
            const float2 r0 = __half22float2(e1[0]);
            const float2 r1 = __half22float2(e1[1]);
            const float2 r2 = __half22float2(e1[2]);
            const float2 r3 = __half22float2(e1[3]);

            float sc0, sc1;
            sc0 = tanh_fast(p0.x + a0.x) * v0.x;
            sc1 = tanh_fast(r0.x + a0.x) * v0.x;
            sc0 = fmaf(tanh_fast(p0.y + a0.y), v0.y, sc0);
            sc1 = fmaf(tanh_fast(r0.y + a0.y), v0.y, sc1);
            sc0 = fmaf(tanh_fast(p1.x + a0.z), v0.z, sc0);
            sc1 = fmaf(tanh_fast(r1.x + a0.z), v0.z, sc1);
            sc0 = fmaf(tanh_fast(p1.y + a0.w), v0.w, sc0);
            sc1 = fmaf(tanh_fast(r1.y + a0.w), v0.w, sc1);
            sc0 = fmaf(tanh_fast(p2.x + a1.x), v1.x, sc0);
            sc1 = fmaf(tanh_fast(r2.x + a1.x), v1.x, sc1);
            sc0 = fmaf(tanh_fast(p2.y + a1.y), v1.y, sc0);
            sc1 = fmaf(tanh_fast(r2.y + a1.y), v1.y, sc1);
            sc0 = fmaf(tanh_fast(p3.x + a1.z), v1.z, sc0);
            sc1 = fmaf(tanh_fast(r3.x + a1.z), v1.z, sc1);
            sc0 = fmaf(tanh_fast(p3.y + a1.w), v1.w, sc0);
            sc1 = fmaf(tanh_fast(r3.y + a1.w), v1.w, sc1);
#pragma unroll
            for (int o = 16; o; o >>= 1) {
                sc0 += __shfl_xor_sync(0xffffffffu, sc0, o);
                sc1 += __shfl_xor_sync(0xffffffffu, sc1, o);
            }
            if (lane == 0) {
                const float e0v = __expf(sc0);
                const int k0 = j0 - qlo;
                if (k0 < QCAP) { wsm[k0] = e0v; nsm[k0] = n0; }
                else           g_scores[j0] = e0v;
                if (h1) {
                    const float e1v = __expf(sc1);
                    const int k1 = j1 - qlo;
                    if (k1 < QCAP) { wsm[k1] = e1v; nsm[k1] = n1; }
                    else           g_scores[j1] = e1v;
                }
            }
        }
    }
    __syncthreads();

    // ---- per-segment exp sums ----
    for (int t = w; t < SEQL; t += 8) {
        const int slo = sbnd[t]     - qlo;
        const int shi = sbnd[t + 1] - qlo;
        float d = 0.0f;
        for (int k = slo + lane; k < shi; k += 32)
            d += (k < QCAP) ? wsm[k] : g_scores[qlo + k];
#pragma unroll
        for (int o = 16; o; o >>= 1) d += __shfl_xor_sync(0xffffffffu, d, o);
        if (lane == 0) sdsum[t] = d;
    }

    // ---- pass 2: float4 grain; group g owns segments {g, g+4, ...} ----
    const int g  = tid >> 6;               // 0..3
    const int h4 = tid & 63;               // float4 index within row
    const float4 s4 = *(reinterpret_cast<const float4*>(
                            ent + (size_t)s[q] * H) + h4);
    const float4 r4 = *(reinterpret_cast<const float4*>(
                            rel + (size_t)r[q] * H) + h4);
    __syncthreads();                        // wsm/nsm/sdsum ready

    float* qout = out + (size_t)q * SEQL * (3 * H);
#pragma unroll 1
    for (int t = g; t < SEQL; t += 4) {
        float* row = qout + (size_t)t * (3 * H);
        float4* rowA = reinterpret_cast<float4*>(row);
        float4* rowS = reinterpret_cast<float4*>(row + H);
        float4* rowR = reinterpret_cast<float4*>(row + 2 * H);
        const int slo = sbnd[t]     - qlo;
        const int shi = sbnd[t + 1] - qlo;

        if (slo >= shi) {
            const float4 z = make_float4(0.f, 0.f, 0.f, 0.f);
            rowA[h4] = z; rowS[h4] = z; rowR[h4] = z;
            continue;
        }
        const float inv = 1.0f / sdsum[t];
        const int c = min(shi, QCAP);

        float4 a0 = make_float4(0.f, 0.f, 0.f, 0.f);
        float4 a1 = make_float4(0.f, 0.f, 0.f, 0.f);
        int k = slo;
        for (; k + 1 < c; k += 2) {
            const float w0 = wsm[k], w1 = wsm[k + 1];
            const float4 e0 = *(reinterpret_cast<const float4*>(
                                    ent + (size_t)nsm[k] * H) + h4);
            const float4 e1 = *(reinterpret_cast<const float4*>(
                                    ent + (size_t)nsm[k + 1] * H) + h4);
            a0.x = fmaf(w0, e0.x, a0.x); a0.y = fmaf(w0, e0.y, a0.y);
            a0.z = fmaf(w0, e0.z, a0.z); a0.w = fmaf(w0, e0.w, a0.w);
            a1.x = fmaf(w1, e1.x, a1.x); a1.y = fmaf(w1, e1.y, a1.y);
            a1.z = fmaf(w1, e1.z, a1.z); a1.w = fmaf(w1, e1.w, a1.w);
        }
        for (; k < c; k++) {
            const float w0 = wsm[k];
            const float4 e0 = *(reinterpret_cast<const float4*>(
                                    ent + (size_t)nsm[k] * H) + h4);
            a0.x = fmaf(w0, e0.x, a0.x); a0.y = fmaf(w0, e0.y, a0.y);
            a0.z = fmaf(w0, e0.z, a0.z); a0.w = fmaf(w0, e0.w, a0.w);
        }
        for (; k < shi; k++) {              // spill path (rare)
            const float w0 = g_scores[qlo + k];
            const float4 e0 = *(reinterpret_cast<const float4*>(
                                    ent + (size_t)nbr_ids[qlo + k] * H) + h4);
            a0.x = fmaf(w0, e0.x, a0.x); a0.y = fmaf(w0, e0.y, a0.y);
            a0.z = fmaf(w0, e0.z, a0.z); a0.w = fmaf(w0, e0.w, a0.w);
        }

        rowA[h4] = make_float4((a0.x + a1.x) * inv, (a0.y + a1.y) * inv,
                               (a0.z + a1.z) * inv, (a0.w + a1.w) * inv);
        rowS[h4] = s4;
        rowR[h4] = r4;
    }
}

// ---------------------------------------------------------------------------
extern "C" void kernel_launch(void* const* d_in, const int* in_sizes, int n_in,
                              void* d_out, int out_size) {
    const int*   s    = (const int*)d_in[0];
    const int*   r    = (const int*)d_in[1];
    const int*   nbr  = (const int*)d_in[2];
    const int*   segi = (const int*)d_in[3];
    const float* ent  = (const float*)d_in[4];
    const float* rel  = (const float*)d_in[5];
    const float* W    = (const float*)d_in[6];
    const float* b    = (const float*)d_in[7];
    const float* v    = (const float*)d_in[8];
    float* out = (float*)d_out;

    cudaFuncSetAttribute(gemm_kernel,
                         cudaFuncAttributeMaxDynamicSharedMemorySize, MM_SMEM);

    prep_kernel<<<64 + (NTOT + 255) / 256, 256>>>(segi, W);
    gemm_kernel<<<AQ_BLOCKS + EW1_BLOCKS, 256, MM_SMEM>>>(ent, s, r, rel, W, b);
    scoreagg_kernel<<<BQ, 256>>>(s, r, nbr, ent, rel, v, out);
}